// round 4
// baseline (speedup 1.0000x reference)
#include <cuda_runtime.h>
#include <cstdint>

#define NN   50000
#define EE   800000
#define PP   4
#define CIN  256
#define DD   256
#define SEMH 128

// ---------------- scratch (device globals; no allocations allowed) ----------
__device__ float g_x[(size_t)PP * NN * DD];      // (h@W)*rsqrt(deg_out)  [P,N,D]
__device__ float g_z[(size_t)PP * NN * DD];      // per-metapath embeddings [P,N,D]
__device__ int   g_deg_out[PP * NN];
__device__ int   g_deg_in [PP * NN];
__device__ int   g_row_start[PP * NN];
__device__ int   g_cursor   [PP * NN];
__device__ int   g_csr_src[(size_t)PP * EE];
__device__ float g_s_sum[PP];
__device__ float g_beta [PP];

// ---------------- 1. zero counters ----------------
__global__ void k_zero() {
    int i = blockIdx.x * blockDim.x + threadIdx.x;
    if (i < PP * NN) { g_deg_out[i] = 0; g_deg_in[i] = 0; }
    if (i < PP) g_s_sum[i] = 0.f;
}

// ---------------- 2. degrees ----------------
__global__ void k_deg(const int* __restrict__ src, const int* __restrict__ dst) {
    int i = blockIdx.x * blockDim.x + threadIdx.x;
    if (i >= PP * EE) return;
    int p = i / EE;
    atomicAdd(&g_deg_out[p * NN + src[i]], 1);
    atomicAdd(&g_deg_in [p * NN + dst[i]], 1);
}

// ---------------- 3. exclusive scan of deg_in -> row_start (per metapath) ---
__global__ void k_scan() {
    const int p = blockIdx.x;
    __shared__ int sh[1024];
    __shared__ int carry;
    if (threadIdx.x == 0) carry = 0;
    __syncthreads();
    for (int base = 0; base < NN; base += 1024) {
        int i = base + threadIdx.x;
        int v = (i < NN) ? g_deg_in[p * NN + i] : 0;
        sh[threadIdx.x] = v;
        __syncthreads();
        // Hillis-Steele inclusive scan
        for (int off = 1; off < 1024; off <<= 1) {
            int t = (threadIdx.x >= off) ? sh[threadIdx.x - off] : 0;
            __syncthreads();
            sh[threadIdx.x] += t;
            __syncthreads();
        }
        int excl = sh[threadIdx.x] - v;
        if (i < NN) {
            int rs = carry + excl;
            g_row_start[p * NN + i] = rs;
            g_cursor   [p * NN + i] = rs;
        }
        __syncthreads();
        if (threadIdx.x == 1023) carry += sh[1023];
        __syncthreads();
    }
}

// ---------------- 4. fill CSR (by dst) ----------------
__global__ void k_fill(const int* __restrict__ src, const int* __restrict__ dst) {
    int i = blockIdx.x * blockDim.x + threadIdx.x;
    if (i >= PP * EE) return;
    int p = i / EE;
    int d = dst[i];
    int pos = atomicAdd(&g_cursor[p * NN + d], 1);
    g_csr_src[(size_t)p * EE + pos] = src[i];
}

// ---------------- 5. feature GEMM: x = (h @ W_p) * rsqrt(max(deg_out,1)) ----
// 128x128 block tile, BK=8, 256 threads, 8x8 per thread
__global__ __launch_bounds__(256) void k_gemm_x(const float* __restrict__ h,
                                                const float* __restrict__ Wg) {
    const int p    = blockIdx.z;
    const int row0 = blockIdx.y * 128;
    const int col0 = blockIdx.x * 128;
    __shared__ float As[8][128];
    __shared__ float Bs[8][128];
    const int tid = threadIdx.x;
    const int tx = tid & 15, ty = tid >> 4;
    const int ar = tid >> 1, ac = (tid & 1) * 4;
    const int br = tid >> 5, bc = (tid & 31) * 4;
    const float* Wp = Wg + (size_t)p * CIN * DD;
    float acc[8][8] = {};
    for (int k0 = 0; k0 < CIN; k0 += 8) {
        float4 av = make_float4(0.f, 0.f, 0.f, 0.f);
        int row = row0 + ar;
        if (row < NN) av = *(const float4*)(h + (size_t)row * CIN + k0 + ac);
        As[ac + 0][ar] = av.x; As[ac + 1][ar] = av.y;
        As[ac + 2][ar] = av.z; As[ac + 3][ar] = av.w;
        *(float4*)&Bs[br][bc] = *(const float4*)(Wp + (size_t)(k0 + br) * DD + col0 + bc);
        __syncthreads();
#pragma unroll
        for (int kk = 0; kk < 8; kk++) {
            float a[8], b[8];
#pragma unroll
            for (int i = 0; i < 8; i++) a[i] = As[kk][ty * 8 + i];
#pragma unroll
            for (int j = 0; j < 8; j++) b[j] = Bs[kk][tx * 8 + j];
#pragma unroll
            for (int i = 0; i < 8; i++)
#pragma unroll
                for (int j = 0; j < 8; j++) acc[i][j] += a[i] * b[j];
        }
        __syncthreads();
    }
#pragma unroll
    for (int i = 0; i < 8; i++) {
        int row = row0 + ty * 8 + i;
        if (row >= NN) break;
        float rs = rsqrtf((float)max(g_deg_out[p * NN + row], 1));
        float* op = g_x + ((size_t)p * NN + row) * DD + col0 + tx * 8;
#pragma unroll
        for (int j = 0; j < 8; j += 4) {
            float4 v;
            v.x = acc[i][j + 0] * rs; v.y = acc[i][j + 1] * rs;
            v.z = acc[i][j + 2] * rs; v.w = acc[i][j + 3] * rs;
            *(float4*)(op + j) = v;
        }
    }
}

// ---------------- 6. aggregate over in-edges (no float atomics) -------------
__global__ __launch_bounds__(256) void k_agg(const float* __restrict__ b_gc, int p) {
    const int n = blockIdx.x;
    const int d = threadIdx.x;
    const int base  = p * NN + n;
    const int start = g_row_start[base];
    const int deg   = g_deg_in[base];
    const float* X  = g_x + (size_t)p * NN * DD;
    const int* cs   = g_csr_src + (size_t)p * EE + start;
    float a0 = 0.f, a1 = 0.f, a2 = 0.f, a3 = 0.f;
    int e = 0;
    for (; e + 4 <= deg; e += 4) {
        int s0 = cs[e], s1 = cs[e + 1], s2 = cs[e + 2], s3 = cs[e + 3];
        a0 += X[(size_t)s0 * DD + d];
        a1 += X[(size_t)s1 * DD + d];
        a2 += X[(size_t)s2 * DD + d];
        a3 += X[(size_t)s3 * DD + d];
    }
    for (; e < deg; e++) a0 += X[(size_t)cs[e] * DD + d];
    float acc = (a0 + a1) + (a2 + a3);
    float rs = rsqrtf((float)max(deg, 1));
    g_z[((size_t)p * NN + n) * DD + d] = acc * rs + b_gc[p * DD + d];
}

// ---------------- 7. semantic attention numerator ---------------------------
// s[n,p] = tanh(z[n,p,:] @ W1 + b1) . w2 ; accumulate sum over n into g_s_sum[p]
__global__ __launch_bounds__(256) void k_sem(const float* __restrict__ W1,
                                             const float* __restrict__ b1,
                                             const float* __restrict__ w2) {
    const int p  = blockIdx.z;
    const int n0 = blockIdx.x * 128;
    __shared__ float As[8][128];
    __shared__ float Bs[8][128];
    __shared__ float sred[128][17];
    __shared__ float sblk[128];
    const int tid = threadIdx.x;
    const int tx = tid & 15, ty = tid >> 4;
    const int ar = tid >> 1, ac = (tid & 1) * 4;
    const int br = tid >> 5, bc = (tid & 31) * 4;
    const float* Z = g_z + (size_t)p * NN * DD;
    float acc[8][8] = {};
    for (int k0 = 0; k0 < DD; k0 += 8) {
        float4 av = make_float4(0.f, 0.f, 0.f, 0.f);
        int row = n0 + ar;
        if (row < NN) av = *(const float4*)(Z + (size_t)row * DD + k0 + ac);
        As[ac + 0][ar] = av.x; As[ac + 1][ar] = av.y;
        As[ac + 2][ar] = av.z; As[ac + 3][ar] = av.w;
        *(float4*)&Bs[br][bc] = *(const float4*)(W1 + (size_t)(k0 + br) * SEMH + bc);
        __syncthreads();
#pragma unroll
        for (int kk = 0; kk < 8; kk++) {
            float a[8], b[8];
#pragma unroll
            for (int i = 0; i < 8; i++) a[i] = As[kk][ty * 8 + i];
#pragma unroll
            for (int j = 0; j < 8; j++) b[j] = Bs[kk][tx * 8 + j];
#pragma unroll
            for (int i = 0; i < 8; i++)
#pragma unroll
                for (int j = 0; j < 8; j++) acc[i][j] += a[i] * b[j];
        }
        __syncthreads();
    }
    // epilogue: tanh, dot with w2, row-reduce
    float b1c[8], w2c[8];
#pragma unroll
    for (int j = 0; j < 8; j++) { b1c[j] = b1[tx * 8 + j]; w2c[j] = w2[tx * 8 + j]; }
#pragma unroll
    for (int i = 0; i < 8; i++) {
        float v = 0.f;
#pragma unroll
        for (int j = 0; j < 8; j++) v += tanhf(acc[i][j] + b1c[j]) * w2c[j];
        sred[ty * 8 + i][tx] = v;
    }
    __syncthreads();
    float sv = 0.f;
    if (tid < 128) {
        int row = n0 + tid;
        if (row < NN) {
#pragma unroll
            for (int t = 0; t < 16; t++) sv += sred[tid][t];
        }
        sblk[tid] = sv;
    }
    __syncthreads();
    for (int off = 64; off > 0; off >>= 1) {
        if (tid < off) sblk[tid] += sblk[tid + off];
        __syncthreads();
    }
    if (tid == 0) atomicAdd(&g_s_sum[p], sblk[0]);
}

// ---------------- 8. beta = softmax(mean over nodes) -------------------------
__global__ void k_beta() {
    if (threadIdx.x == 0 && blockIdx.x == 0) {
        float m[PP]; float mx = -1e30f;
        for (int p = 0; p < PP; p++) { m[p] = g_s_sum[p] / (float)NN; mx = fmaxf(mx, m[p]); }
        float se = 0.f;
        for (int p = 0; p < PP; p++) { m[p] = expf(m[p] - mx); se += m[p]; }
        for (int p = 0; p < PP; p++) g_beta[p] = m[p] / se;
    }
}

// ---------------- 9. combine: out = sum_p beta[p] * z_p ---------------------
__global__ void k_comb(float* __restrict__ out) {
    const size_t q = (size_t)NN * DD / 4;  // float4 count per metapath
    size_t i = (size_t)blockIdx.x * blockDim.x + threadIdx.x;
    if (i >= q) return;
    float b0 = g_beta[0], b1 = g_beta[1], b2 = g_beta[2], b3 = g_beta[3];
    const float4* z = (const float4*)g_z;
    float4 v0 = z[i], v1 = z[q + i], v2 = z[2 * q + i], v3 = z[3 * q + i];
    float4 o;
    o.x = b0 * v0.x + b1 * v1.x + b2 * v2.x + b3 * v3.x;
    o.y = b0 * v0.y + b1 * v1.y + b2 * v2.y + b3 * v3.y;
    o.z = b0 * v0.z + b1 * v1.z + b2 * v2.z + b3 * v3.z;
    o.w = b0 * v0.w + b1 * v1.w + b2 * v2.w + b3 * v3.w;
    ((float4*)out)[i] = o;
}

// ---------------- launch --------------------------------------------------
extern "C" void kernel_launch(void* const* d_in, const int* in_sizes, int n_in,
                              void* d_out, int out_size) {
    const float* h    = (const float*)d_in[0];
    const int*   src  = (const int*)  d_in[1];
    const int*   dst  = (const int*)  d_in[2];
    const float* W_gc = (const float*)d_in[3];
    const float* b_gc = (const float*)d_in[4];
    const float* W1   = (const float*)d_in[5];
    const float* b1   = (const float*)d_in[6];
    const float* w2   = (const float*)d_in[7];
    float* out = (float*)d_out;

    k_zero<<<(PP * NN + 255) / 256, 256>>>();
    k_deg<<<(PP * EE + 255) / 256, 256>>>(src, dst);
    k_scan<<<PP, 1024>>>();
    k_fill<<<(PP * EE + 255) / 256, 256>>>(src, dst);
    k_gemm_x<<<dim3(DD / 128, (NN + 127) / 128, PP), 256>>>(h, W_gc);
    for (int p = 0; p < PP; p++)
        k_agg<<<NN, 256>>>(b_gc, p);   // per-p launch keeps x_p L2-resident
    k_sem<<<dim3((NN + 127) / 128, 1, PP), 256>>>(W1, b1, w2);
    k_beta<<<1, 32>>>();
    k_comb<<<(int)(((size_t)NN * DD / 4 + 255) / 256), 256>>>(out);
}

// round 7
// speedup vs baseline: 1.4001x; 1.4001x over previous
#include <cuda_runtime.h>
#include <cuda_bf16.h>
#include <cstdint>

#define NN   50000
#define EE   800000
#define PP   4
#define CIN  256
#define DD   256
#define SEMH 128

// mma tiling
#define BM 128
#define BN 128
#define BK 32
#define SA 40                    // padded smem row stride (bf16 elems) = 80B
#define MTILES ((NN + BM - 1) / BM)

// ---------------- scratch (device globals; no allocations allowed) ----------
__device__ float g_x[(size_t)PP * NN * DD];      // (h@W)*rsqrt(deg_out)  [P,N,D]
__device__ float g_z[(size_t)PP * NN * DD];      // per-metapath embeddings [P,N,D]
__device__ __nv_bfloat16 g_zb[(size_t)PP * NN * DD];   // bf16 copy of z
__device__ int   g_deg_out[PP * NN];
__device__ int   g_deg_in [PP * NN];
__device__ int   g_row_start[PP * NN];
__device__ int   g_cursor   [PP * NN];
__device__ int   g_csr_src[(size_t)PP * EE];
__device__ float g_s_sum[PP];
__device__ float g_beta [PP];
// bf16x2 split staging
__device__ __nv_bfloat16 g_h_hi[(size_t)NN * CIN];
__device__ __nv_bfloat16 g_h_lo[(size_t)NN * CIN];
__device__ __nv_bfloat16 g_wt_hi[(size_t)PP * DD * CIN];   // W^T: [p][n][k]
__device__ __nv_bfloat16 g_wt_lo[(size_t)PP * DD * CIN];
__device__ __nv_bfloat16 g_w1t_hi[(size_t)SEMH * DD];      // W1^T: [n][k]
__device__ __nv_bfloat16 g_w1t_lo[(size_t)SEMH * DD];

// ---------------- mma.sync helper (portable PTX, works on plain sm_103) -----
__device__ __forceinline__ void mma_bf16(float c[4],
                                         uint32_t a0, uint32_t a1, uint32_t a2, uint32_t a3,
                                         uint32_t b0, uint32_t b1) {
    asm volatile(
        "mma.sync.aligned.m16n8k16.row.col.f32.bf16.bf16.f32 "
        "{%0,%1,%2,%3}, {%4,%5,%6,%7}, {%8,%9}, {%0,%1,%2,%3};"
        : "+f"(c[0]), "+f"(c[1]), "+f"(c[2]), "+f"(c[3])
        : "r"(a0), "r"(a1), "r"(a2), "r"(a3), "r"(b0), "r"(b1));
}
__device__ __forceinline__ uint32_t ld32(const __nv_bfloat16* p) {
    return *(const uint32_t*)p;
}

// ---------------- 1. zero counters ----------------
__global__ void k_zero() {
    int i = blockIdx.x * blockDim.x + threadIdx.x;
    if (i < PP * NN) { g_deg_out[i] = 0; g_deg_in[i] = 0; }
    if (i < PP) g_s_sum[i] = 0.f;
}

// ---------------- 2. degrees ----------------
__global__ void k_deg(const int* __restrict__ src, const int* __restrict__ dst) {
    int i = blockIdx.x * blockDim.x + threadIdx.x;
    if (i >= PP * EE) return;
    int p = i / EE;
    atomicAdd(&g_deg_out[p * NN + src[i]], 1);
    atomicAdd(&g_deg_in [p * NN + dst[i]], 1);
}

// ---------------- 3. exclusive scan of deg_in -> row_start ------------------
__global__ void k_scan() {
    const int p = blockIdx.x;
    __shared__ int sh[1024];
    __shared__ int carry;
    if (threadIdx.x == 0) carry = 0;
    __syncthreads();
    for (int base = 0; base < NN; base += 1024) {
        int i = base + threadIdx.x;
        int v = (i < NN) ? g_deg_in[p * NN + i] : 0;
        sh[threadIdx.x] = v;
        __syncthreads();
        for (int off = 1; off < 1024; off <<= 1) {
            int t = (threadIdx.x >= off) ? sh[threadIdx.x - off] : 0;
            __syncthreads();
            sh[threadIdx.x] += t;
            __syncthreads();
        }
        int excl = sh[threadIdx.x] - v;
        if (i < NN) {
            int rs = carry + excl;
            g_row_start[p * NN + i] = rs;
            g_cursor   [p * NN + i] = rs;
        }
        __syncthreads();
        if (threadIdx.x == 1023) carry += sh[1023];
        __syncthreads();
    }
}

// ---------------- 4. fill CSR (by dst) ----------------
__global__ void k_fill(const int* __restrict__ src, const int* __restrict__ dst) {
    int i = blockIdx.x * blockDim.x + threadIdx.x;
    if (i >= PP * EE) return;
    int p = i / EE;
    int d = dst[i];
    int pos = atomicAdd(&g_cursor[p * NN + d], 1);
    g_csr_src[(size_t)p * EE + pos] = src[i];
}

// ---------------- 5a. bf16x2 split of h -------------------------------------
__global__ void k_split_h(const float* __restrict__ h) {
    size_t i = (size_t)blockIdx.x * blockDim.x + threadIdx.x;
    if (i >= (size_t)NN * CIN) return;
    float x = h[i];
    __nv_bfloat16 hi = __float2bfloat16(x);
    __nv_bfloat16 lo = __float2bfloat16(x - __bfloat162float(hi));
    g_h_hi[i] = hi; g_h_lo[i] = lo;
}

// ---------------- 5b. bf16x2 split + transpose of W_gc ----------------------
// W_gc [p][k][n] (row-major) -> g_wt [p][n][k]
__global__ void k_split_w(const float* __restrict__ Wg) {
    int i = blockIdx.x * blockDim.x + threadIdx.x;
    if (i >= PP * CIN * DD) return;
    int p = i / (CIN * DD);
    int r = i % (CIN * DD);
    int k = r / DD;
    int n = r % DD;
    float x = Wg[i];
    __nv_bfloat16 hi = __float2bfloat16(x);
    __nv_bfloat16 lo = __float2bfloat16(x - __bfloat162float(hi));
    size_t d = ((size_t)p * DD + n) * CIN + k;
    g_wt_hi[d] = hi; g_wt_lo[d] = lo;
}

// ---------------- 5c. bf16x2 split + transpose of W1 ------------------------
// W1 [k=256][n=128] -> g_w1t [n][k]
__global__ void k_split_w1(const float* __restrict__ W1) {
    int i = blockIdx.x * blockDim.x + threadIdx.x;
    if (i >= DD * SEMH) return;
    int k = i / SEMH;
    int n = i % SEMH;
    float x = W1[i];
    __nv_bfloat16 hi = __float2bfloat16(x);
    __nv_bfloat16 lo = __float2bfloat16(x - __bfloat162float(hi));
    size_t d = (size_t)n * DD + k;
    g_w1t_hi[d] = hi; g_w1t_lo[d] = lo;
}

// ---------------- 6. tensor GEMM: x = (h @ W_p) * rsqrt(deg_out) ------------
// grid (MTILES, DD/BN, PP), 256 threads = 8 warps, warp tile 32x64.
// bf16x2 split, 3 mma per k-step, fp32 accum.
__global__ __launch_bounds__(256) void k_gemm_x() {
    __shared__ __nv_bfloat16 sAh[BM * SA];
    __shared__ __nv_bfloat16 sAl[BM * SA];
    __shared__ __nv_bfloat16 sBh[BN * SA];
    __shared__ __nv_bfloat16 sBl[BN * SA];

    const int tid   = threadIdx.x;
    const int lane  = tid & 31;
    const int wid   = tid >> 5;
    const int wm    = wid & 3;            // warp M index (32 rows)
    const int wn    = wid >> 2;           // warp N index (64 cols)
    const int g     = lane >> 2;          // groupID 0..7
    const int tig   = lane & 3;           // thread-in-group
    const int p     = blockIdx.z;
    const int m0    = blockIdx.x * BM;
    const int n0    = blockIdx.y * BN;

    const __nv_bfloat16* Whi = g_wt_hi + (size_t)p * DD * CIN;
    const __nv_bfloat16* Wlo = g_wt_lo + (size_t)p * DD * CIN;

    float c[2][8][4];
#pragma unroll
    for (int mi = 0; mi < 2; mi++)
#pragma unroll
        for (int ni = 0; ni < 8; ni++)
#pragma unroll
            for (int j = 0; j < 4; j++) c[mi][ni][j] = 0.f;

    for (int k0 = 0; k0 < CIN; k0 += BK) {
        // load tiles: 128 rows x 4 chunks of 8 bf16
        for (int idx = tid; idx < BM * (BK / 8); idx += 256) {
            int r  = idx >> 2;
            int cc = (idx & 3) * 8;
            int sr = m0 + r;
            float4 vh = make_float4(0.f, 0.f, 0.f, 0.f), vl = vh;
            if (sr < NN) {
                vh = *(const float4*)(g_h_hi + (size_t)sr * CIN + k0 + cc);
                vl = *(const float4*)(g_h_lo + (size_t)sr * CIN + k0 + cc);
            }
            *(float4*)&sAh[r * SA + cc] = vh;
            *(float4*)&sAl[r * SA + cc] = vl;
            // B tile (always in range)
            *(float4*)&sBh[r * SA + cc] = *(const float4*)(Whi + (size_t)(n0 + r) * CIN + k0 + cc);
            *(float4*)&sBl[r * SA + cc] = *(const float4*)(Wlo + (size_t)(n0 + r) * CIN + k0 + cc);
        }
        __syncthreads();

#pragma unroll
        for (int ks = 0; ks < BK; ks += 16) {
            const int c0 = ks + tig * 2;
            uint32_t ah[2][4], al[2][4];
#pragma unroll
            for (int mi = 0; mi < 2; mi++) {
                int r0 = wm * 32 + mi * 16 + g;
                ah[mi][0] = ld32(&sAh[r0 * SA + c0]);
                ah[mi][1] = ld32(&sAh[(r0 + 8) * SA + c0]);
                ah[mi][2] = ld32(&sAh[r0 * SA + c0 + 8]);
                ah[mi][3] = ld32(&sAh[(r0 + 8) * SA + c0 + 8]);
                al[mi][0] = ld32(&sAl[r0 * SA + c0]);
                al[mi][1] = ld32(&sAl[(r0 + 8) * SA + c0]);
                al[mi][2] = ld32(&sAl[r0 * SA + c0 + 8]);
                al[mi][3] = ld32(&sAl[(r0 + 8) * SA + c0 + 8]);
            }
#pragma unroll
            for (int ni = 0; ni < 8; ni++) {
                int nb = wn * 64 + ni * 8 + g;
                uint32_t bh0 = ld32(&sBh[nb * SA + c0]);
                uint32_t bh1 = ld32(&sBh[nb * SA + c0 + 8]);
                uint32_t bl0 = ld32(&sBl[nb * SA + c0]);
                uint32_t bl1 = ld32(&sBl[nb * SA + c0 + 8]);
#pragma unroll
                for (int mi = 0; mi < 2; mi++) {
                    mma_bf16(c[mi][ni], ah[mi][0], ah[mi][1], ah[mi][2], ah[mi][3], bh0, bh1);
                    mma_bf16(c[mi][ni], ah[mi][0], ah[mi][1], ah[mi][2], ah[mi][3], bl0, bl1);
                    mma_bf16(c[mi][ni], al[mi][0], al[mi][1], al[mi][2], al[mi][3], bh0, bh1);
                }
            }
        }
        __syncthreads();
    }

    // epilogue: scale by rsqrt(deg_out) and store
#pragma unroll
    for (int mi = 0; mi < 2; mi++) {
        int row0 = m0 + wm * 32 + mi * 16 + g;
        int row1 = row0 + 8;
        float rs0 = (row0 < NN) ? rsqrtf((float)max(g_deg_out[p * NN + row0], 1)) : 0.f;
        float rs1 = (row1 < NN) ? rsqrtf((float)max(g_deg_out[p * NN + row1], 1)) : 0.f;
#pragma unroll
        for (int ni = 0; ni < 8; ni++) {
            int col = n0 + wn * 64 + ni * 8 + tig * 2;
            if (row0 < NN) {
                float2 v = make_float2(c[mi][ni][0] * rs0, c[mi][ni][1] * rs0);
                *(float2*)(g_x + ((size_t)p * NN + row0) * DD + col) = v;
            }
            if (row1 < NN) {
                float2 v = make_float2(c[mi][ni][2] * rs1, c[mi][ni][3] * rs1);
                *(float2*)(g_x + ((size_t)p * NN + row1) * DD + col) = v;
            }
        }
    }
}

// ---------------- 7. aggregate over in-edges (no float atomics) -------------
__global__ __launch_bounds__(256) void k_agg(const float* __restrict__ b_gc, int p) {
    const int n = blockIdx.x;
    const int d = threadIdx.x;
    const int base  = p * NN + n;
    const int start = g_row_start[base];
    const int deg   = g_deg_in[base];
    const float* X  = g_x + (size_t)p * NN * DD;
    const int* cs   = g_csr_src + (size_t)p * EE + start;
    float a0 = 0.f, a1 = 0.f, a2 = 0.f, a3 = 0.f;
    int e = 0;
    for (; e + 4 <= deg; e += 4) {
        int s0 = cs[e], s1 = cs[e + 1], s2 = cs[e + 2], s3 = cs[e + 3];
        a0 += X[(size_t)s0 * DD + d];
        a1 += X[(size_t)s1 * DD + d];
        a2 += X[(size_t)s2 * DD + d];
        a3 += X[(size_t)s3 * DD + d];
    }
    for (; e < deg; e++) a0 += X[(size_t)cs[e] * DD + d];
    float acc = (a0 + a1) + (a2 + a3);
    float rs = rsqrtf((float)max(deg, 1));
    float val = acc * rs + b_gc[p * DD + d];
    size_t oi = ((size_t)p * NN + n) * DD + d;
    g_z[oi]  = val;
    g_zb[oi] = __float2bfloat16(val);
}

// ---------------- 8. semantic attention via mma -----------------------------
// s[n,p] = tanh(z@W1 + b1).w2 ; sum over nodes -> g_s_sum[p]
// z single bf16 (random per-node error averages out); W1 split hi/lo (2 mma).
// grid (MTILES, 1, PP), 256 threads, warp tile 32x64, SEMH=128 full in N.
__global__ __launch_bounds__(256) void k_sem_tc(const float* __restrict__ b1,
                                                const float* __restrict__ w2) {
    __shared__ __nv_bfloat16 sA [BM * SA];
    __shared__ __nv_bfloat16 sBh[SEMH * SA];
    __shared__ __nv_bfloat16 sBl[SEMH * SA];
    __shared__ float sred[128][9];
    __shared__ float sblk[128];

    const int tid  = threadIdx.x;
    const int lane = tid & 31;
    const int wid  = tid >> 5;
    const int wm   = wid & 3;
    const int wn   = wid >> 2;
    const int g    = lane >> 2;
    const int tig  = lane & 3;
    const int p    = blockIdx.z;
    const int m0   = blockIdx.x * BM;

    const __nv_bfloat16* Z = g_zb + (size_t)p * NN * DD;

    float c[2][8][4];
#pragma unroll
    for (int mi = 0; mi < 2; mi++)
#pragma unroll
        for (int ni = 0; ni < 8; ni++)
#pragma unroll
            for (int j = 0; j < 4; j++) c[mi][ni][j] = 0.f;

    for (int k0 = 0; k0 < DD; k0 += BK) {
        for (int idx = tid; idx < BM * (BK / 8); idx += 256) {
            int r  = idx >> 2;
            int cc = (idx & 3) * 8;
            int sr = m0 + r;
            float4 v = make_float4(0.f, 0.f, 0.f, 0.f);
            if (sr < NN) v = *(const float4*)(Z + (size_t)sr * DD + k0 + cc);
            *(float4*)&sA[r * SA + cc] = v;
        }
        for (int idx = tid; idx < SEMH * (BK / 8); idx += 256) {
            int r  = idx >> 2;
            int cc = (idx & 3) * 8;
            *(float4*)&sBh[r * SA + cc] = *(const float4*)(g_w1t_hi + (size_t)r * DD + k0 + cc);
            *(float4*)&sBl[r * SA + cc] = *(const float4*)(g_w1t_lo + (size_t)r * DD + k0 + cc);
        }
        __syncthreads();

#pragma unroll
        for (int ks = 0; ks < BK; ks += 16) {
            const int c0 = ks + tig * 2;
            uint32_t a[2][4];
#pragma unroll
            for (int mi = 0; mi < 2; mi++) {
                int r0 = wm * 32 + mi * 16 + g;
                a[mi][0] = ld32(&sA[r0 * SA + c0]);
                a[mi][1] = ld32(&sA[(r0 + 8) * SA + c0]);
                a[mi][2] = ld32(&sA[r0 * SA + c0 + 8]);
                a[mi][3] = ld32(&sA[(r0 + 8) * SA + c0 + 8]);
            }
#pragma unroll
            for (int ni = 0; ni < 8; ni++) {
                int nb = wn * 64 + ni * 8 + g;
                uint32_t bh0 = ld32(&sBh[nb * SA + c0]);
                uint32_t bh1 = ld32(&sBh[nb * SA + c0 + 8]);
                uint32_t bl0 = ld32(&sBl[nb * SA + c0]);
                uint32_t bl1 = ld32(&sBl[nb * SA + c0 + 8]);
#pragma unroll
                for (int mi = 0; mi < 2; mi++) {
                    mma_bf16(c[mi][ni], a[mi][0], a[mi][1], a[mi][2], a[mi][3], bh0, bh1);
                    mma_bf16(c[mi][ni], a[mi][0], a[mi][1], a[mi][2], a[mi][3], bl0, bl1);
                }
            }
        }
        __syncthreads();
    }

    // epilogue: tanh(.+b1).w2, reduce over SEMH
    float vrow[2][2] = {{0.f, 0.f}, {0.f, 0.f}};
#pragma unroll
    for (int ni = 0; ni < 8; ni++) {
        int col = wn * 64 + ni * 8 + tig * 2;
        float b1a = b1[col], b1b = b1[col + 1];
        float w2a = w2[col], w2b = w2[col + 1];
#pragma unroll
        for (int mi = 0; mi < 2; mi++) {
            vrow[mi][0] += tanhf(c[mi][ni][0] + b1a) * w2a + tanhf(c[mi][ni][1] + b1b) * w2b;
            vrow[mi][1] += tanhf(c[mi][ni][2] + b1a) * w2a + tanhf(c[mi][ni][3] + b1b) * w2b;
        }
    }
#pragma unroll
    for (int mi = 0; mi < 2; mi++) {
        int r0 = wm * 32 + mi * 16 + g;
        sred[r0][wn * 4 + tig]     = vrow[mi][0];
        sred[r0 + 8][wn * 4 + tig] = vrow[mi][1];
    }
    __syncthreads();
    if (tid < 128) {
        float sv = 0.f;
        if (m0 + tid < NN) {
#pragma unroll
            for (int t = 0; t < 8; t++) sv += sred[tid][t];
        }
        sblk[tid] = sv;
    }
    __syncthreads();
    for (int off = 64; off > 0; off >>= 1) {
        if (tid < off) sblk[tid] += sblk[tid + off];
        __syncthreads();
    }
    if (tid == 0) atomicAdd(&g_s_sum[p], sblk[0]);
}

// ---------------- 9. beta = softmax(mean over nodes) ------------------------
__global__ void k_beta() {
    if (threadIdx.x == 0 && blockIdx.x == 0) {
        float m[PP]; float mx = -1e30f;
        for (int p = 0; p < PP; p++) { m[p] = g_s_sum[p] / (float)NN; mx = fmaxf(mx, m[p]); }
        float se = 0.f;
        for (int p = 0; p < PP; p++) { m[p] = expf(m[p] - mx); se += m[p]; }
        for (int p = 0; p < PP; p++) g_beta[p] = m[p] / se;
    }
}

// ---------------- 10. combine: out = sum_p beta[p] * z_p --------------------
__global__ void k_comb(float* __restrict__ out) {
    const size_t q = (size_t)NN * DD / 4;
    size_t i = (size_t)blockIdx.x * blockDim.x + threadIdx.x;
    if (i >= q) return;
    float b0 = g_beta[0], b1 = g_beta[1], b2 = g_beta[2], b3 = g_beta[3];
    const float4* z = (const float4*)g_z;
    float4 v0 = z[i], v1 = z[q + i], v2 = z[2 * q + i], v3 = z[3 * q + i];
    float4 o;
    o.x = b0 * v0.x + b1 * v1.x + b2 * v2.x + b3 * v3.x;
    o.y = b0 * v0.y + b1 * v1.y + b2 * v2.y + b3 * v3.y;
    o.z = b0 * v0.z + b1 * v1.z + b2 * v2.z + b3 * v3.z;
    o.w = b0 * v0.w + b1 * v1.w + b2 * v2.w + b3 * v3.w;
    ((float4*)out)[i] = o;
}

// ---------------- launch ----------------------------------------------------
extern "C" void kernel_launch(void* const* d_in, const int* in_sizes, int n_in,
                              void* d_out, int out_size) {
    const float* h    = (const float*)d_in[0];
    const int*   src  = (const int*)  d_in[1];
    const int*   dst  = (const int*)  d_in[2];
    const float* W_gc = (const float*)d_in[3];
    const float* b_gc = (const float*)d_in[4];
    const float* W1   = (const float*)d_in[5];
    const float* b1   = (const float*)d_in[6];
    const float* w2   = (const float*)d_in[7];
    float* out = (float*)d_out;

    k_zero<<<(PP * NN + 255) / 256, 256>>>();
    k_deg<<<(PP * EE + 255) / 256, 256>>>(src, dst);
    k_scan<<<PP, 1024>>>();
    k_fill<<<(PP * EE + 255) / 256, 256>>>(src, dst);
    k_split_h<<<(int)(((size_t)NN * CIN + 255) / 256), 256>>>(h);
    k_split_w<<<(PP * CIN * DD + 255) / 256, 256>>>(W_gc);
    k_split_w1<<<(DD * SEMH + 255) / 256, 256>>>(W1);
    k_gemm_x<<<dim3(MTILES, DD / BN, PP), 256>>>();
    for (int p = 0; p < PP; p++)
        k_agg<<<NN, 256>>>(b_gc, p);
    k_sem_tc<<<dim3(MTILES, 1, PP), 256>>>(b1, w2);
    k_beta<<<1, 32>>>();
    k_comb<<<(int)(((size_t)NN * DD / 4 + 255) / 256), 256>>>(out);
}

// round 9
// speedup vs baseline: 1.8830x; 1.3449x over previous
#include <cuda_runtime.h>
#include <cuda_bf16.h>
#include <cuda_fp16.h>
#include <cstdint>

#define NN   50000
#define EE   800000
#define PP   4
#define CIN  256
#define DD   256
#define SEMH 128

// mma tiling
#define BM 128
#define BN 128
#define BK 32
#define SA 40                    // padded smem row stride (bf16 elems) = 80B (16B-aligned)
#define MTILES ((NN + BM - 1) / BM)
#define TILE_ELEMS (BM * SA)             // bf16 elems per tile
#define TILE_BYTES (TILE_ELEMS * 2)      // 10240
#define GEMM_SMEM (2 * 4 * TILE_BYTES)   // 81920 (double buffer x 4 arrays)

// ---------------- scratch (device globals; no allocations allowed) ----------
__device__ __half g_x[(size_t)PP * NN * DD];     // fp16 (h@W)*rsqrt(deg_out)
__device__ float g_z[(size_t)PP * NN * DD];      // per-metapath embeddings [P,N,D]
__device__ __nv_bfloat16 g_zb[(size_t)PP * NN * DD];   // bf16 copy of z
__device__ int   g_deg_out[PP * NN];
__device__ int   g_deg_in [PP * NN];
__device__ int   g_row_start[PP * NN];
__device__ int   g_cursor   [PP * NN];
__device__ int   g_csr_src[(size_t)PP * EE];
__device__ float g_s_sum[PP];
__device__ float g_beta [PP];
// bf16x2 split staging
__device__ __nv_bfloat16 g_h_hi[(size_t)NN * CIN];
__device__ __nv_bfloat16 g_h_lo[(size_t)NN * CIN];
__device__ __nv_bfloat16 g_wt_hi[(size_t)PP * DD * CIN];   // W^T: [p][n][k]
__device__ __nv_bfloat16 g_wt_lo[(size_t)PP * DD * CIN];
__device__ __nv_bfloat16 g_w1t_hi[(size_t)SEMH * DD];      // W1^T: [n][k]
__device__ __nv_bfloat16 g_w1t_lo[(size_t)SEMH * DD];

// ---------------- helpers ---------------------------------------------------
__device__ __forceinline__ void mma_bf16(float c[4],
                                         uint32_t a0, uint32_t a1, uint32_t a2, uint32_t a3,
                                         uint32_t b0, uint32_t b1) {
    asm volatile(
        "mma.sync.aligned.m16n8k16.row.col.f32.bf16.bf16.f32 "
        "{%0,%1,%2,%3}, {%4,%5,%6,%7}, {%8,%9}, {%0,%1,%2,%3};"
        : "+f"(c[0]), "+f"(c[1]), "+f"(c[2]), "+f"(c[3])
        : "r"(a0), "r"(a1), "r"(a2), "r"(a3), "r"(b0), "r"(b1));
}
__device__ __forceinline__ uint32_t ld32(const __nv_bfloat16* p) {
    return *(const uint32_t*)p;
}
__device__ __forceinline__ uint32_t smem_u32(const void* p) {
    uint32_t a;
    asm("{ .reg .u64 t; cvta.to.shared.u64 t, %1; cvt.u32.u64 %0, t; }" : "=r"(a) : "l"(p));
    return a;
}
__device__ __forceinline__ void cp16(uint32_t sdst, const void* gsrc, int src_sz) {
    asm volatile("cp.async.cg.shared.global [%0], [%1], 16, %2;"
                 :: "r"(sdst), "l"(gsrc), "r"(src_sz) : "memory");
}
#define CP_COMMIT() asm volatile("cp.async.commit_group;" ::: "memory")
#define CP_WAIT(n)  asm volatile("cp.async.wait_group %0;" :: "n"(n) : "memory")

// ---------------- 1. zero counters ----------------
__global__ void k_zero() {
    int i = blockIdx.x * blockDim.x + threadIdx.x;
    if (i < PP * NN) { g_deg_out[i] = 0; g_deg_in[i] = 0; }
    if (i < PP) g_s_sum[i] = 0.f;
}

// ---------------- 2. degrees ----------------
__global__ void k_deg(const int* __restrict__ src, const int* __restrict__ dst) {
    int i = blockIdx.x * blockDim.x + threadIdx.x;
    if (i >= PP * EE) return;
    int p = i / EE;
    atomicAdd(&g_deg_out[p * NN + src[i]], 1);
    atomicAdd(&g_deg_in [p * NN + dst[i]], 1);
}

// ---------------- 3. exclusive scan of deg_in -> row_start ------------------
__global__ void k_scan() {
    const int p = blockIdx.x;
    __shared__ int sh[1024];
    __shared__ int carry;
    if (threadIdx.x == 0) carry = 0;
    __syncthreads();
    for (int base = 0; base < NN; base += 1024) {
        int i = base + threadIdx.x;
        int v = (i < NN) ? g_deg_in[p * NN + i] : 0;
        sh[threadIdx.x] = v;
        __syncthreads();
        for (int off = 1; off < 1024; off <<= 1) {
            int t = (threadIdx.x >= off) ? sh[threadIdx.x - off] : 0;
            __syncthreads();
            sh[threadIdx.x] += t;
            __syncthreads();
        }
        int excl = sh[threadIdx.x] - v;
        if (i < NN) {
            int rs = carry + excl;
            g_row_start[p * NN + i] = rs;
            g_cursor   [p * NN + i] = rs;
        }
        __syncthreads();
        if (threadIdx.x == 1023) carry += sh[1023];
        __syncthreads();
    }
}

// ---------------- 4. fill CSR (by dst) ----------------
__global__ void k_fill(const int* __restrict__ src, const int* __restrict__ dst) {
    int i = blockIdx.x * blockDim.x + threadIdx.x;
    if (i >= PP * EE) return;
    int p = i / EE;
    int d = dst[i];
    int pos = atomicAdd(&g_cursor[p * NN + d], 1);
    g_csr_src[(size_t)p * EE + pos] = src[i];
}

// ---------------- 5a. bf16x2 split of h -------------------------------------
__global__ void k_split_h(const float* __restrict__ h) {
    size_t i = (size_t)blockIdx.x * blockDim.x + threadIdx.x;
    if (i >= (size_t)NN * CIN) return;
    float x = h[i];
    __nv_bfloat16 hi = __float2bfloat16(x);
    __nv_bfloat16 lo = __float2bfloat16(x - __bfloat162float(hi));
    g_h_hi[i] = hi; g_h_lo[i] = lo;
}

// ---------------- 5b. bf16x2 split + transpose of W_gc ----------------------
__global__ void k_split_w(const float* __restrict__ Wg) {
    int i = blockIdx.x * blockDim.x + threadIdx.x;
    if (i >= PP * CIN * DD) return;
    int p = i / (CIN * DD);
    int r = i % (CIN * DD);
    int k = r / DD;
    int n = r % DD;
    float x = Wg[i];
    __nv_bfloat16 hi = __float2bfloat16(x);
    __nv_bfloat16 lo = __float2bfloat16(x - __bfloat162float(hi));
    size_t d = ((size_t)p * DD + n) * CIN + k;
    g_wt_hi[d] = hi; g_wt_lo[d] = lo;
}

// ---------------- 5c. bf16x2 split + transpose of W1 ------------------------
__global__ void k_split_w1(const float* __restrict__ W1) {
    int i = blockIdx.x * blockDim.x + threadIdx.x;
    if (i >= DD * SEMH) return;
    int k = i / SEMH;
    int n = i % SEMH;
    float x = W1[i];
    __nv_bfloat16 hi = __float2bfloat16(x);
    __nv_bfloat16 lo = __float2bfloat16(x - __bfloat162float(hi));
    size_t d = (size_t)n * DD + k;
    g_w1t_hi[d] = hi; g_w1t_lo[d] = lo;
}

// ---------------- 6. tensor GEMM: x = fp16((h @ W_p) * rsqrt(deg_out)) ------
// grid (MTILES, DD/BN, PP), 256 threads = 8 warps, warp tile 32x64.
// bf16x2 split (3 mma / k-step), cp.async double-buffered smem.
__global__ __launch_bounds__(256) void k_gemm_x() {
    extern __shared__ __nv_bfloat16 smg[];
    const uint32_t sbase = smem_u32(smg);

    const int tid   = threadIdx.x;
    const int lane  = tid & 31;
    const int wid   = tid >> 5;
    const int wm    = wid & 3;
    const int wn    = wid >> 2;
    const int g     = lane >> 2;
    const int tig   = lane & 3;
    const int p     = blockIdx.z;
    const int m0    = blockIdx.x * BM;
    const int n0    = blockIdx.y * BN;

    const __nv_bfloat16* Whi = g_wt_hi + (size_t)p * DD * CIN;
    const __nv_bfloat16* Wlo = g_wt_lo + (size_t)p * DD * CIN;

    float c[2][8][4];
#pragma unroll
    for (int mi = 0; mi < 2; mi++)
#pragma unroll
        for (int ni = 0; ni < 8; ni++)
#pragma unroll
            for (int j = 0; j < 4; j++) c[mi][ni][j] = 0.f;

    auto issue = [&](int kch, int buf) {
        const int k0 = kch * BK;
        const uint32_t b = sbase + (uint32_t)buf * 4u * TILE_BYTES;
#pragma unroll
        for (int it = 0; it < 2; it++) {
            int idx = tid + it * 256;            // BM*(BK/8)=512 chunks
            int r  = idx >> 2;
            int cc = (idx & 3) * 8;
            uint32_t soff = (uint32_t)(r * SA + cc) * 2u;
            int sr = m0 + r;
            int ok = (sr < NN);
            size_t aoff = (size_t)(ok ? sr : 0) * CIN + k0 + cc;
            cp16(b + 0 * TILE_BYTES + soff, g_h_hi + aoff, ok ? 16 : 0);
            cp16(b + 1 * TILE_BYTES + soff, g_h_lo + aoff, ok ? 16 : 0);
            size_t boff = (size_t)(n0 + r) * CIN + k0 + cc;
            cp16(b + 2 * TILE_BYTES + soff, Whi + boff, 16);
            cp16(b + 3 * TILE_BYTES + soff, Wlo + boff, 16);
        }
    };

    const int NK = CIN / BK;   // 8
    issue(0, 0);
    CP_COMMIT();
    for (int kc = 0; kc < NK; kc++) {
        const int buf = kc & 1;
        if (kc + 1 < NK) {
            issue(kc + 1, buf ^ 1);
            CP_COMMIT();
            CP_WAIT(1);
        } else {
            CP_WAIT(0);
        }
        __syncthreads();

        const __nv_bfloat16* sAh = smg + (size_t)buf * 4 * TILE_ELEMS;
        const __nv_bfloat16* sAl = sAh + TILE_ELEMS;
        const __nv_bfloat16* sBh = sAl + TILE_ELEMS;
        const __nv_bfloat16* sBl = sBh + TILE_ELEMS;

#pragma unroll
        for (int ks = 0; ks < BK; ks += 16) {
            const int c0 = ks + tig * 2;
            uint32_t ah[2][4], al[2][4];
#pragma unroll
            for (int mi = 0; mi < 2; mi++) {
                int r0 = wm * 32 + mi * 16 + g;
                ah[mi][0] = ld32(&sAh[r0 * SA + c0]);
                ah[mi][1] = ld32(&sAh[(r0 + 8) * SA + c0]);
                ah[mi][2] = ld32(&sAh[r0 * SA + c0 + 8]);
                ah[mi][3] = ld32(&sAh[(r0 + 8) * SA + c0 + 8]);
                al[mi][0] = ld32(&sAl[r0 * SA + c0]);
                al[mi][1] = ld32(&sAl[(r0 + 8) * SA + c0]);
                al[mi][2] = ld32(&sAl[r0 * SA + c0 + 8]);
                al[mi][3] = ld32(&sAl[(r0 + 8) * SA + c0 + 8]);
            }
#pragma unroll
            for (int ni = 0; ni < 8; ni++) {
                int nb = wn * 64 + ni * 8 + g;
                uint32_t bh0 = ld32(&sBh[nb * SA + c0]);
                uint32_t bh1 = ld32(&sBh[nb * SA + c0 + 8]);
                uint32_t bl0 = ld32(&sBl[nb * SA + c0]);
                uint32_t bl1 = ld32(&sBl[nb * SA + c0 + 8]);
#pragma unroll
                for (int mi = 0; mi < 2; mi++) {
                    mma_bf16(c[mi][ni], ah[mi][0], ah[mi][1], ah[mi][2], ah[mi][3], bh0, bh1);
                    mma_bf16(c[mi][ni], ah[mi][0], ah[mi][1], ah[mi][2], ah[mi][3], bl0, bl1);
                    mma_bf16(c[mi][ni], al[mi][0], al[mi][1], al[mi][2], al[mi][3], bh0, bh1);
                }
            }
        }
        __syncthreads();
    }

    // epilogue: scale by rsqrt(deg_out), store fp16
#pragma unroll
    for (int mi = 0; mi < 2; mi++) {
        int row0 = m0 + wm * 32 + mi * 16 + g;
        int row1 = row0 + 8;
        float rs0 = (row0 < NN) ? rsqrtf((float)max(g_deg_out[p * NN + row0], 1)) : 0.f;
        float rs1 = (row1 < NN) ? rsqrtf((float)max(g_deg_out[p * NN + row1], 1)) : 0.f;
#pragma unroll
        for (int ni = 0; ni < 8; ni++) {
            int col = n0 + wn * 64 + ni * 8 + tig * 2;
            if (row0 < NN) {
                __half2 v = __floats2half2_rn(c[mi][ni][0] * rs0, c[mi][ni][1] * rs0);
                *(__half2*)(g_x + ((size_t)p * NN + row0) * DD + col) = v;
            }
            if (row1 < NN) {
                __half2 v = __floats2half2_rn(c[mi][ni][2] * rs1, c[mi][ni][3] * rs1);
                *(__half2*)(g_x + ((size_t)p * NN + row1) * DD + col) = v;
            }
        }
    }
}

// ---------------- 7. aggregate over in-edges (fp16 gather, fp32 accum) ------
// 256 threads = 4 edge-groups x 64 threads; each thread covers 4 dims (8B).
__global__ __launch_bounds__(256) void k_agg(const float* __restrict__ b_gc, int p) {
    const int n   = blockIdx.x;
    const int tid = threadIdx.x;
    const int grp = tid >> 6;
    const int t   = tid & 63;
    const int base  = p * NN + n;
    const int start = g_row_start[base];
    const int deg   = g_deg_in[base];
    const __half* X = g_x + (size_t)p * NN * DD;
    const int* cs   = g_csr_src + (size_t)p * EE + start;

    float4 acc = make_float4(0.f, 0.f, 0.f, 0.f);
    int e = grp;
    for (; e + 4 < deg; e += 8) {
        int s0 = cs[e], s1 = cs[e + 4];
        uint2 v0 = *(const uint2*)(X + (size_t)s0 * DD + t * 4);
        uint2 v1 = *(const uint2*)(X + (size_t)s1 * DD + t * 4);
        float2 a0 = __half22float2(*(__half2*)&v0.x);
        float2 a1 = __half22float2(*(__half2*)&v0.y);
        float2 b0 = __half22float2(*(__half2*)&v1.x);
        float2 b1 = __half22float2(*(__half2*)&v1.y);
        acc.x += a0.x + b0.x; acc.y += a0.y + b0.y;
        acc.z += a1.x + b1.x; acc.w += a1.y + b1.y;
    }
    if (e < deg) {
        int s0 = cs[e];
        uint2 v0 = *(const uint2*)(X + (size_t)s0 * DD + t * 4);
        float2 a0 = __half22float2(*(__half2*)&v0.x);
        float2 a1 = __half22float2(*(__half2*)&v0.y);
        acc.x += a0.x; acc.y += a0.y; acc.z += a1.x; acc.w += a1.y;
    }

    __shared__ float sacc[4][256];
    *(float4*)&sacc[grp][t * 4] = acc;
    __syncthreads();

    float v = sacc[0][tid] + sacc[1][tid] + sacc[2][tid] + sacc[3][tid];
    float rs = rsqrtf((float)max(deg, 1));
    float val = v * rs + b_gc[p * DD + tid];
    size_t oi = ((size_t)p * NN + n) * DD + tid;
    g_z[oi]  = val;
    g_zb[oi] = __float2bfloat16(val);
}

// ---------------- 8. semantic attention via mma -----------------------------
__global__ __launch_bounds__(256) void k_sem_tc(const float* __restrict__ b1,
                                                const float* __restrict__ w2) {
    __shared__ __nv_bfloat16 sA [BM * SA];
    __shared__ __nv_bfloat16 sBh[SEMH * SA];
    __shared__ __nv_bfloat16 sBl[SEMH * SA];
    __shared__ float sred[128][9];
    __shared__ float sblk[128];

    const int tid  = threadIdx.x;
    const int lane = tid & 31;
    const int wid  = tid >> 5;
    const int wm   = wid & 3;
    const int wn   = wid >> 2;
    const int g    = lane >> 2;
    const int tig  = lane & 3;
    const int p    = blockIdx.z;
    const int m0   = blockIdx.x * BM;

    const __nv_bfloat16* Z = g_zb + (size_t)p * NN * DD;

    float c[2][8][4];
#pragma unroll
    for (int mi = 0; mi < 2; mi++)
#pragma unroll
        for (int ni = 0; ni < 8; ni++)
#pragma unroll
            for (int j = 0; j < 4; j++) c[mi][ni][j] = 0.f;

    for (int k0 = 0; k0 < DD; k0 += BK) {
        for (int idx = tid; idx < BM * (BK / 8); idx += 256) {
            int r  = idx >> 2;
            int cc = (idx & 3) * 8;
            int sr = m0 + r;
            float4 v = make_float4(0.f, 0.f, 0.f, 0.f);
            if (sr < NN) v = *(const float4*)(Z + (size_t)sr * DD + k0 + cc);
            *(float4*)&sA[r * SA + cc] = v;
        }
        for (int idx = tid; idx < SEMH * (BK / 8); idx += 256) {
            int r  = idx >> 2;
            int cc = (idx & 3) * 8;
            *(float4*)&sBh[r * SA + cc] = *(const float4*)(g_w1t_hi + (size_t)r * DD + k0 + cc);
            *(float4*)&sBl[r * SA + cc] = *(const float4*)(g_w1t_lo + (size_t)r * DD + k0 + cc);
        }
        __syncthreads();

#pragma unroll
        for (int ks = 0; ks < BK; ks += 16) {
            const int c0 = ks + tig * 2;
            uint32_t a[2][4];
#pragma unroll
            for (int mi = 0; mi < 2; mi++) {
                int r0 = wm * 32 + mi * 16 + g;
                a[mi][0] = ld32(&sA[r0 * SA + c0]);
                a[mi][1] = ld32(&sA[(r0 + 8) * SA + c0]);
                a[mi][2] = ld32(&sA[r0 * SA + c0 + 8]);
                a[mi][3] = ld32(&sA[(r0 + 8) * SA + c0 + 8]);
            }
#pragma unroll
            for (int ni = 0; ni < 8; ni++) {
                int nb = wn * 64 + ni * 8 + g;
                uint32_t bh0 = ld32(&sBh[nb * SA + c0]);
                uint32_t bh1 = ld32(&sBh[nb * SA + c0 + 8]);
                uint32_t bl0 = ld32(&sBl[nb * SA + c0]);
                uint32_t bl1 = ld32(&sBl[nb * SA + c0 + 8]);
#pragma unroll
                for (int mi = 0; mi < 2; mi++) {
                    mma_bf16(c[mi][ni], a[mi][0], a[mi][1], a[mi][2], a[mi][3], bh0, bh1);
                    mma_bf16(c[mi][ni], a[mi][0], a[mi][1], a[mi][2], a[mi][3], bl0, bl1);
                }
            }
        }
        __syncthreads();
    }

    float vrow[2][2] = {{0.f, 0.f}, {0.f, 0.f}};
#pragma unroll
    for (int ni = 0; ni < 8; ni++) {
        int col = wn * 64 + ni * 8 + tig * 2;
        float b1a = b1[col], b1b = b1[col + 1];
        float w2a = w2[col], w2b = w2[col + 1];
#pragma unroll
        for (int mi = 0; mi < 2; mi++) {
            vrow[mi][0] += tanhf(c[mi][ni][0] + b1a) * w2a + tanhf(c[mi][ni][1] + b1b) * w2b;
            vrow[mi][1] += tanhf(c[mi][ni][2] + b1a) * w2a + tanhf(c[mi][ni][3] + b1b) * w2b;
        }
    }
#pragma unroll
    for (int mi = 0; mi < 2; mi++) {
        int r0 = wm * 32 + mi * 16 + g;
        sred[r0][wn * 4 + tig]     = vrow[mi][0];
        sred[r0 + 8][wn * 4 + tig] = vrow[mi][1];
    }
    __syncthreads();
    if (tid < 128) {
        float sv = 0.f;
        if (m0 + tid < NN) {
#pragma unroll
            for (int t = 0; t < 8; t++) sv += sred[tid][t];
        }
        sblk[tid] = sv;
    }
    __syncthreads();
    for (int off = 64; off > 0; off >>= 1) {
        if (tid < off) sblk[tid] += sblk[tid + off];
        __syncthreads();
    }
    if (tid == 0) atomicAdd(&g_s_sum[p], sblk[0]);
}

// ---------------- 9. beta = softmax(mean over nodes) ------------------------
__global__ void k_beta() {
    if (threadIdx.x == 0 && blockIdx.x == 0) {
        float m[PP]; float mx = -1e30f;
        for (int p = 0; p < PP; p++) { m[p] = g_s_sum[p] / (float)NN; mx = fmaxf(mx, m[p]); }
        float se = 0.f;
        for (int p = 0; p < PP; p++) { m[p] = expf(m[p] - mx); se += m[p]; }
        for (int p = 0; p < PP; p++) g_beta[p] = m[p] / se;
    }
}

// ---------------- 10. combine: out = sum_p beta[p] * z_p --------------------
__global__ void k_comb(float* __restrict__ out) {
    const size_t q = (size_t)NN * DD / 4;
    size_t i = (size_t)blockIdx.x * blockDim.x + threadIdx.x;
    if (i >= q) return;
    float b0 = g_beta[0], b1 = g_beta[1], b2 = g_beta[2], b3 = g_beta[3];
    const float4* z = (const float4*)g_z;
    float4 v0 = z[i], v1 = z[q + i], v2 = z[2 * q + i], v3 = z[3 * q + i];
    float4 o;
    o.x = b0 * v0.x + b1 * v1.x + b2 * v2.x + b3 * v3.x;
    o.y = b0 * v0.y + b1 * v1.y + b2 * v2.y + b3 * v3.y;
    o.z = b0 * v0.z + b1 * v1.z + b2 * v2.z + b3 * v3.z;
    o.w = b0 * v0.w + b1 * v1.w + b2 * v2.w + b3 * v3.w;
    ((float4*)out)[i] = o;
}

// ---------------- launch ----------------------------------------------------
extern "C" void kernel_launch(void* const* d_in, const int* in_sizes, int n_in,
                              void* d_out, int out_size) {
    const float* h    = (const float*)d_in[0];
    const int*   src  = (const int*)  d_in[1];
    const int*   dst  = (const int*)  d_in[2];
    const float* W_gc = (const float*)d_in[3];
    const float* b_gc = (const float*)d_in[4];
    const float* W1   = (const float*)d_in[5];
    const float* b1   = (const float*)d_in[6];
    const float* w2   = (const float*)d_in[7];
    float* out = (float*)d_out;

    static bool attr_set = false;
    if (!attr_set) {
        cudaFuncSetAttribute(k_gemm_x, cudaFuncAttributeMaxDynamicSharedMemorySize,
                             GEMM_SMEM);
        attr_set = true;
    }

    k_zero<<<(PP * NN + 255) / 256, 256>>>();
    k_deg<<<(PP * EE + 255) / 256, 256>>>(src, dst);
    k_scan<<<PP, 1024>>>();
    k_fill<<<(PP * EE + 255) / 256, 256>>>(src, dst);
    k_split_h<<<(int)(((size_t)NN * CIN + 255) / 256), 256>>>(h);
    k_split_w<<<(PP * CIN * DD + 255) / 256, 256>>>(W_gc);
    k_split_w1<<<(DD * SEMH + 255) / 256, 256>>>(W1);
    k_gemm_x<<<dim3(MTILES, DD / BN, PP), 256, GEMM_SMEM>>>();
    for (int p = 0; p < PP; p++)
        k_agg<<<NN, 256>>>(b_gc, p);
    k_sem_tc<<<dim3(MTILES, 1, PP), 256>>>(b1, w2);
    k_beta<<<1, 32>>>();
    k_comb<<<(int)(((size_t)NN * DD / 4 + 255) / 256), 256>>>(out);
}

// round 10
// speedup vs baseline: 2.0734x; 1.1011x over previous
#include <cuda_runtime.h>
#include <cuda_fp16.h>
#include <cstdint>

#define NN   50000
#define EE   800000
#define PP   4
#define CIN  256
#define DD   256
#define SEMH 128

// mma tiling
#define BM 128
#define BN 128
#define BK 32
#define SA 40                    // padded smem row stride (fp16 elems) = 80B (16B-aligned)
#define MTILES ((NN + BM - 1) / BM)
#define TILE_ELEMS (BM * SA)             // fp16 elems per tile
#define TILE_BYTES (TILE_ELEMS * 2)      // 10240
#define GEMM_SMEM (2 * 3 * TILE_BYTES)   // 61440 (double buffer x 3 arrays)

// ---------------- scratch (device globals; no allocations allowed) ----------
__device__ __half g_x[(size_t)PP * NN * DD];     // fp16 (h@W)*rsqrt(deg_out)
__device__ __half g_z[(size_t)PP * NN * DD];     // fp16 per-metapath embeddings
__device__ int   g_deg_out[PP * NN];
__device__ int   g_deg_in [PP * NN];
__device__ int   g_row_start[PP * NN];
__device__ int   g_cursor   [PP * NN];
__device__ int   g_csr_src[(size_t)PP * EE];
__device__ float g_s_sum[PP];
__device__ float g_beta [PP];
// fp16 split staging
__device__ __half g_h_hi[(size_t)NN * CIN];
__device__ __half g_h_lo[(size_t)NN * CIN];
__device__ __half g_wt  [(size_t)PP * DD * CIN];   // fp16(W^T): [p][n][k]
__device__ __half g_w1t_hi[(size_t)SEMH * DD];     // W1^T hi: [n][k]
__device__ __half g_w1t_lo[(size_t)SEMH * DD];     // W1^T lo

// ---------------- helpers ---------------------------------------------------
__device__ __forceinline__ void mma_f16(float c[4],
                                        uint32_t a0, uint32_t a1, uint32_t a2, uint32_t a3,
                                        uint32_t b0, uint32_t b1) {
    asm volatile(
        "mma.sync.aligned.m16n8k16.row.col.f32.f16.f16.f32 "
        "{%0,%1,%2,%3}, {%4,%5,%6,%7}, {%8,%9}, {%0,%1,%2,%3};"
        : "+f"(c[0]), "+f"(c[1]), "+f"(c[2]), "+f"(c[3])
        : "r"(a0), "r"(a1), "r"(a2), "r"(a3), "r"(b0), "r"(b1));
}
__device__ __forceinline__ uint32_t ld32(const void* p) {
    return *(const uint32_t*)p;
}
__device__ __forceinline__ uint32_t smem_u32(const void* p) {
    uint32_t a;
    asm("{ .reg .u64 t; cvta.to.shared.u64 t, %1; cvt.u32.u64 %0, t; }" : "=r"(a) : "l"(p));
    return a;
}
__device__ __forceinline__ void cp16(uint32_t sdst, const void* gsrc, int src_sz) {
    asm volatile("cp.async.cg.shared.global [%0], [%1], 16, %2;"
                 :: "r"(sdst), "l"(gsrc), "r"(src_sz) : "memory");
}
#define CP_COMMIT() asm volatile("cp.async.commit_group;" ::: "memory")
#define CP_WAIT(n)  asm volatile("cp.async.wait_group %0;" :: "n"(n) : "memory")

// ---------------- 1. zero counters ----------------
__global__ void k_zero() {
    int i = blockIdx.x * blockDim.x + threadIdx.x;
    if (i < PP * NN) { g_deg_out[i] = 0; g_deg_in[i] = 0; }
    if (i < PP) g_s_sum[i] = 0.f;
}

// ---------------- 2. degrees ----------------
__global__ void k_deg(const int* __restrict__ src, const int* __restrict__ dst) {
    int i = blockIdx.x * blockDim.x + threadIdx.x;
    if (i >= PP * EE) return;
    int p = i / EE;
    atomicAdd(&g_deg_out[p * NN + src[i]], 1);
    atomicAdd(&g_deg_in [p * NN + dst[i]], 1);
}

// ---------------- 3. exclusive scan of deg_in -> row_start ------------------
__global__ void k_scan() {
    const int p = blockIdx.x;
    __shared__ int sh[1024];
    __shared__ int carry;
    if (threadIdx.x == 0) carry = 0;
    __syncthreads();
    for (int base = 0; base < NN; base += 1024) {
        int i = base + threadIdx.x;
        int v = (i < NN) ? g_deg_in[p * NN + i] : 0;
        sh[threadIdx.x] = v;
        __syncthreads();
        for (int off = 1; off < 1024; off <<= 1) {
            int t = (threadIdx.x >= off) ? sh[threadIdx.x - off] : 0;
            __syncthreads();
            sh[threadIdx.x] += t;
            __syncthreads();
        }
        int excl = sh[threadIdx.x] - v;
        if (i < NN) {
            int rs = carry + excl;
            g_row_start[p * NN + i] = rs;
            g_cursor   [p * NN + i] = rs;
        }
        __syncthreads();
        if (threadIdx.x == 1023) carry += sh[1023];
        __syncthreads();
    }
}

// ---------------- 4. fill CSR (by dst) ----------------
__global__ void k_fill(const int* __restrict__ src, const int* __restrict__ dst) {
    int i = blockIdx.x * blockDim.x + threadIdx.x;
    if (i >= PP * EE) return;
    int p = i / EE;
    int d = dst[i];
    int pos = atomicAdd(&g_cursor[p * NN + d], 1);
    g_csr_src[(size_t)p * EE + pos] = src[i];
}

// ---------------- 5a. fp16 hi/lo split of h ---------------------------------
__global__ void k_split_h(const float* __restrict__ h) {
    size_t i = (size_t)blockIdx.x * blockDim.x + threadIdx.x;
    if (i >= (size_t)NN * CIN) return;
    float x = h[i];
    __half hi = __float2half_rn(x);
    __half lo = __float2half_rn(x - __half2float(hi));
    g_h_hi[i] = hi; g_h_lo[i] = lo;
}

// ---------------- 5b. fp16 transpose of W_gc --------------------------------
// W_gc [p][k][n] (row-major) -> g_wt [p][n][k]  (hi only; lo term dropped)
__global__ void k_split_w(const float* __restrict__ Wg) {
    int i = blockIdx.x * blockDim.x + threadIdx.x;
    if (i >= PP * CIN * DD) return;
    int p = i / (CIN * DD);
    int r = i % (CIN * DD);
    int k = r / DD;
    int n = r % DD;
    g_wt[((size_t)p * DD + n) * CIN + k] = __float2half_rn(Wg[i]);
}

// ---------------- 5c. fp16 hi/lo split + transpose of W1 --------------------
__global__ void k_split_w1(const float* __restrict__ W1) {
    int i = blockIdx.x * blockDim.x + threadIdx.x;
    if (i >= DD * SEMH) return;
    int k = i / SEMH;
    int n = i % SEMH;
    float x = W1[i];
    __half hi = __float2half_rn(x);
    __half lo = __float2half_rn(x - __half2float(hi));
    size_t d = (size_t)n * DD + k;
    g_w1t_hi[d] = hi; g_w1t_lo[d] = lo;
}

// ---------------- 6. tensor GEMM: x = fp16((h @ W_p) * rsqrt(deg_out)) ------
// grid (MTILES, DD/BN, PP), 256 threads = 8 warps, warp tile 32x64.
// fp16 hi/lo split of A, single fp16 B (2 mma / k-step), cp.async double buffer.
__global__ __launch_bounds__(256) void k_gemm_x() {
    extern __shared__ __half smg[];
    const uint32_t sbase = smem_u32(smg);

    const int tid   = threadIdx.x;
    const int lane  = tid & 31;
    const int wid   = tid >> 5;
    const int wm    = wid & 3;
    const int wn    = wid >> 2;
    const int g     = lane >> 2;
    const int tig   = lane & 3;
    const int p     = blockIdx.z;
    const int m0    = blockIdx.x * BM;
    const int n0    = blockIdx.y * BN;

    const __half* Wt = g_wt + (size_t)p * DD * CIN;

    float c[2][8][4];
#pragma unroll
    for (int mi = 0; mi < 2; mi++)
#pragma unroll
        for (int ni = 0; ni < 8; ni++)
#pragma unroll
            for (int j = 0; j < 4; j++) c[mi][ni][j] = 0.f;

    auto issue = [&](int kch, int buf) {
        const int k0 = kch * BK;
        const uint32_t b = sbase + (uint32_t)buf * 3u * TILE_BYTES;
#pragma unroll
        for (int it = 0; it < 2; it++) {
            int idx = tid + it * 256;            // BM*(BK/8)=512 chunks
            int r  = idx >> 2;
            int cc = (idx & 3) * 8;
            uint32_t soff = (uint32_t)(r * SA + cc) * 2u;
            int sr = m0 + r;
            int ok = (sr < NN);
            size_t aoff = (size_t)(ok ? sr : 0) * CIN + k0 + cc;
            cp16(b + 0 * TILE_BYTES + soff, g_h_hi + aoff, ok ? 16 : 0);
            cp16(b + 1 * TILE_BYTES + soff, g_h_lo + aoff, ok ? 16 : 0);
            size_t boff = (size_t)(n0 + r) * CIN + k0 + cc;
            cp16(b + 2 * TILE_BYTES + soff, Wt + boff, 16);
        }
    };

    const int NK = CIN / BK;   // 8
    issue(0, 0);
    CP_COMMIT();
    for (int kc = 0; kc < NK; kc++) {
        const int buf = kc & 1;
        if (kc + 1 < NK) {
            issue(kc + 1, buf ^ 1);
            CP_COMMIT();
            CP_WAIT(1);
        } else {
            CP_WAIT(0);
        }
        __syncthreads();

        const __half* sAh = smg + (size_t)buf * 3 * TILE_ELEMS;
        const __half* sAl = sAh + TILE_ELEMS;
        const __half* sB  = sAl + TILE_ELEMS;

#pragma unroll
        for (int ks = 0; ks < BK; ks += 16) {
            const int c0 = ks + tig * 2;
            uint32_t ah[2][4], al[2][4];
#pragma unroll
            for (int mi = 0; mi < 2; mi++) {
                int r0 = wm * 32 + mi * 16 + g;
                ah[mi][0] = ld32(&sAh[r0 * SA + c0]);
                ah[mi][1] = ld32(&sAh[(r0 + 8) * SA + c0]);
                ah[mi][2] = ld32(&sAh[r0 * SA + c0 + 8]);
                ah[mi][3] = ld32(&sAh[(r0 + 8) * SA + c0 + 8]);
                al[mi][0] = ld32(&sAl[r0 * SA + c0]);
                al[mi][1] = ld32(&sAl[(r0 + 8) * SA + c0]);
                al[mi][2] = ld32(&sAl[r0 * SA + c0 + 8]);
                al[mi][3] = ld32(&sAl[(r0 + 8) * SA + c0 + 8]);
            }
#pragma unroll
            for (int ni = 0; ni < 8; ni++) {
                int nb = wn * 64 + ni * 8 + g;
                uint32_t b0 = ld32(&sB[nb * SA + c0]);
                uint32_t b1 = ld32(&sB[nb * SA + c0 + 8]);
#pragma unroll
                for (int mi = 0; mi < 2; mi++) {
                    mma_f16(c[mi][ni], ah[mi][0], ah[mi][1], ah[mi][2], ah[mi][3], b0, b1);
                    mma_f16(c[mi][ni], al[mi][0], al[mi][1], al[mi][2], al[mi][3], b0, b1);
                }
            }
        }
        __syncthreads();
    }

    // epilogue: scale by rsqrt(deg_out), store fp16
#pragma unroll
    for (int mi = 0; mi < 2; mi++) {
        int row0 = m0 + wm * 32 + mi * 16 + g;
        int row1 = row0 + 8;
        float rs0 = (row0 < NN) ? rsqrtf((float)max(g_deg_out[p * NN + row0], 1)) : 0.f;
        float rs1 = (row1 < NN) ? rsqrtf((float)max(g_deg_out[p * NN + row1], 1)) : 0.f;
#pragma unroll
        for (int ni = 0; ni < 8; ni++) {
            int col = n0 + wn * 64 + ni * 8 + tig * 2;
            if (row0 < NN) {
                __half2 v = __floats2half2_rn(c[mi][ni][0] * rs0, c[mi][ni][1] * rs0);
                *(__half2*)(g_x + ((size_t)p * NN + row0) * DD + col) = v;
            }
            if (row1 < NN) {
                __half2 v = __floats2half2_rn(c[mi][ni][2] * rs1, c[mi][ni][3] * rs1);
                *(__half2*)(g_x + ((size_t)p * NN + row1) * DD + col) = v;
            }
        }
    }
}

// ---------------- 7. aggregate over in-edges (fp16 gather, fp32 accum) ------
// 256 threads = 4 edge-groups x 64 threads; each thread covers 4 dims (8B).
__global__ __launch_bounds__(256) void k_agg(const float* __restrict__ b_gc, int p) {
    const int n   = blockIdx.x;
    const int tid = threadIdx.x;
    const int grp = tid >> 6;
    const int t   = tid & 63;
    const int base  = p * NN + n;
    const int start = g_row_start[base];
    const int deg   = g_deg_in[base];
    const __half* X = g_x + (size_t)p * NN * DD;
    const int* cs   = g_csr_src + (size_t)p * EE + start;

    float4 acc = make_float4(0.f, 0.f, 0.f, 0.f);
    int e = grp;
    for (; e + 4 < deg; e += 8) {
        int s0 = cs[e], s1 = cs[e + 4];
        uint2 v0 = *(const uint2*)(X + (size_t)s0 * DD + t * 4);
        uint2 v1 = *(const uint2*)(X + (size_t)s1 * DD + t * 4);
        float2 a0 = __half22float2(*(__half2*)&v0.x);
        float2 a1 = __half22float2(*(__half2*)&v0.y);
        float2 b0 = __half22float2(*(__half2*)&v1.x);
        float2 b1 = __half22float2(*(__half2*)&v1.y);
        acc.x += a0.x + b0.x; acc.y += a0.y + b0.y;
        acc.z += a1.x + b1.x; acc.w += a1.y + b1.y;
    }
    if (e < deg) {
        int s0 = cs[e];
        uint2 v0 = *(const uint2*)(X + (size_t)s0 * DD + t * 4);
        float2 a0 = __half22float2(*(__half2*)&v0.x);
        float2 a1 = __half22float2(*(__half2*)&v0.y);
        acc.x += a0.x; acc.y += a0.y; acc.z += a1.x; acc.w += a1.y;
    }

    __shared__ float sacc[4][256];
    *(float4*)&sacc[grp][t * 4] = acc;
    __syncthreads();

    __shared__ float sval[256];
    {
        float v = sacc[0][tid] + sacc[1][tid] + sacc[2][tid] + sacc[3][tid];
        float rs = rsqrtf((float)max(deg, 1));
        sval[tid] = v * rs + b_gc[p * DD + tid];
    }
    __syncthreads();
    if (tid < 64) {
        __half2 h0 = __floats2half2_rn(sval[tid * 4 + 0], sval[tid * 4 + 1]);
        __half2 h1 = __floats2half2_rn(sval[tid * 4 + 2], sval[tid * 4 + 3]);
        uint2 pk; pk.x = *(uint32_t*)&h0; pk.y = *(uint32_t*)&h1;
        *(uint2*)(g_z + ((size_t)p * NN + n) * DD + tid * 4) = pk;
    }
}

// ---------------- 8. semantic attention via fp16 mma ------------------------
// s[n,p] = tanh(z@W1 + b1).w2 ; sum over nodes -> g_s_sum[p]
// z fp16 single; W1 split hi/lo fp16 (2 mma) to keep the node-mean unbiased.
__global__ __launch_bounds__(256) void k_sem_tc(const float* __restrict__ b1,
                                                const float* __restrict__ w2) {
    __shared__ __half sA [BM * SA];
    __shared__ __half sBh[SEMH * SA];
    __shared__ __half sBl[SEMH * SA];
    __shared__ float sred[128][9];
    __shared__ float sblk[128];

    const int tid  = threadIdx.x;
    const int lane = tid & 31;
    const int wid  = tid >> 5;
    const int wm   = wid & 3;
    const int wn   = wid >> 2;
    const int g    = lane >> 2;
    const int tig  = lane & 3;
    const int p    = blockIdx.z;
    const int m0   = blockIdx.x * BM;

    const __half* Z = g_z + (size_t)p * NN * DD;

    float c[2][8][4];
#pragma unroll
    for (int mi = 0; mi < 2; mi++)
#pragma unroll
        for (int ni = 0; ni < 8; ni++)
#pragma unroll
            for (int j = 0; j < 4; j++) c[mi][ni][j] = 0.f;

    for (int k0 = 0; k0 < DD; k0 += BK) {
        for (int idx = tid; idx < BM * (BK / 8); idx += 256) {
            int r  = idx >> 2;
            int cc = (idx & 3) * 8;
            int sr = m0 + r;
            float4 v = make_float4(0.f, 0.f, 0.f, 0.f);
            if (sr < NN) v = *(const float4*)(Z + (size_t)sr * DD + k0 + cc);
            *(float4*)&sA[r * SA + cc] = v;
        }
        for (int idx = tid; idx < SEMH * (BK / 8); idx += 256) {
            int r  = idx >> 2;
            int cc = (idx & 3) * 8;
            *(float4*)&sBh[r * SA + cc] = *(const float4*)(g_w1t_hi + (size_t)r * DD + k0 + cc);
            *(float4*)&sBl[r * SA + cc] = *(const float4*)(g_w1t_lo + (size_t)r * DD + k0 + cc);
        }
        __syncthreads();

#pragma unroll
        for (int ks = 0; ks < BK; ks += 16) {
            const int c0 = ks + tig * 2;
            uint32_t a[2][4];
#pragma unroll
            for (int mi = 0; mi < 2; mi++) {
                int r0 = wm * 32 + mi * 16 + g;
                a[mi][0] = ld32(&sA[r0 * SA + c0]);
                a[mi][1] = ld32(&sA[(r0 + 8) * SA + c0]);
                a[mi][2] = ld32(&sA[r0 * SA + c0 + 8]);
                a[mi][3] = ld32(&sA[(r0 + 8) * SA + c0 + 8]);
            }
#pragma unroll
            for (int ni = 0; ni < 8; ni++) {
                int nb = wn * 64 + ni * 8 + g;
                uint32_t bh0 = ld32(&sBh[nb * SA + c0]);
                uint32_t bh1 = ld32(&sBh[nb * SA + c0 + 8]);
                uint32_t bl0 = ld32(&sBl[nb * SA + c0]);
                uint32_t bl1 = ld32(&sBl[nb * SA + c0 + 8]);
#pragma unroll
                for (int mi = 0; mi < 2; mi++) {
                    mma_f16(c[mi][ni], a[mi][0], a[mi][1], a[mi][2], a[mi][3], bh0, bh1);
                    mma_f16(c[mi][ni], a[mi][0], a[mi][1], a[mi][2], a[mi][3], bl0, bl1);
                }
            }
        }
        __syncthreads();
    }

    float vrow[2][2] = {{0.f, 0.f}, {0.f, 0.f}};
#pragma unroll
    for (int ni = 0; ni < 8; ni++) {
        int col = wn * 64 + ni * 8 + tig * 2;
        float b1a = b1[col], b1b = b1[col + 1];
        float w2a = w2[col], w2b = w2[col + 1];
#pragma unroll
        for (int mi = 0; mi < 2; mi++) {
            vrow[mi][0] += tanhf(c[mi][ni][0] + b1a) * w2a + tanhf(c[mi][ni][1] + b1b) * w2b;
            vrow[mi][1] += tanhf(c[mi][ni][2] + b1a) * w2a + tanhf(c[mi][ni][3] + b1b) * w2b;
        }
    }
#pragma unroll
    for (int mi = 0; mi < 2; mi++) {
        int r0 = wm * 32 + mi * 16 + g;
        sred[r0][wn * 4 + tig]     = vrow[mi][0];
        sred[r0 + 8][wn * 4 + tig] = vrow[mi][1];
    }
    __syncthreads();
    if (tid < 128) {
        float sv = 0.f;
        if (m0 + tid < NN) {
#pragma unroll
            for (int t = 0; t < 8; t++) sv += sred[tid][t];
        }
        sblk[tid] = sv;
    }
    __syncthreads();
    for (int off = 64; off > 0; off >>= 1) {
        if (tid < off) sblk[tid] += sblk[tid + off];
        __syncthreads();
    }
    if (tid == 0) atomicAdd(&g_s_sum[p], sblk[0]);
}

// ---------------- 9. beta = softmax(mean over nodes) ------------------------
__global__ void k_beta() {
    if (threadIdx.x == 0 && blockIdx.x == 0) {
        float m[PP]; float mx = -1e30f;
        for (int p = 0; p < PP; p++) { m[p] = g_s_sum[p] / (float)NN; mx = fmaxf(mx, m[p]); }
        float se = 0.f;
        for (int p = 0; p < PP; p++) { m[p] = expf(m[p] - mx); se += m[p]; }
        for (int p = 0; p < PP; p++) g_beta[p] = m[p] / se;
    }
}

// ---------------- 10. combine: out = sum_p beta[p] * z_p (fp16 -> fp32) -----
__global__ void k_comb(float* __restrict__ out) {
    const size_t q = (size_t)NN * DD / 4;   // half4 (8B) chunks per metapath
    size_t i = (size_t)blockIdx.x * blockDim.x + threadIdx.x;
    if (i >= q) return;
    float b0 = g_beta[0], b1 = g_beta[1], b2 = g_beta[2], b3 = g_beta[3];
    const uint2* z = (const uint2*)g_z;
    uint2 u0 = z[i], u1 = z[q + i], u2 = z[2 * q + i], u3 = z[3 * q + i];
    float2 p0a = __half22float2(*(__half2*)&u0.x), p0b = __half22float2(*(__half2*)&u0.y);
    float2 p1a = __half22float2(*(__half2*)&u1.x), p1b = __half22float2(*(__half2*)&u1.y);
    float2 p2a = __half22float2(*(__half2*)&u2.x), p2b = __half22float2(*(__half2*)&u2.y);
    float2 p3a = __half22float2(*(__half2*)&u3.x), p3b = __half22float2(*(__half2*)&u3.y);
    float4 o;
    o.x = b0 * p0a.x + b1 * p1a.x + b2 * p2a.x + b3 * p3a.x;
    o.y = b0 * p0a.y + b1 * p1a.y + b2 * p2a.y + b3 * p3a.y;
    o.z = b0 * p0b.x + b1 * p1b.x + b2 * p2b.x + b3 * p3b.x;
    o.w = b0 * p0b.y + b1 * p1b.y + b2 * p2b.y + b3 * p3b.y;
    ((float4*)out)[i] = o;
}

// ---------------- launch ----------------------------------------------------
extern "C" void kernel_launch(void* const* d_in, const int* in_sizes, int n_in,
                              void* d_out, int out_size) {
    const float* h    = (const float*)d_in[0];
    const int*   src  = (const int*)  d_in[1];
    const int*   dst  = (const int*)  d_in[2];
    const float* W_gc = (const float*)d_in[3];
    const float* b_gc = (const float*)d_in[4];
    const float* W1   = (const float*)d_in[5];
    const float* b1   = (const float*)d_in[6];
    const float* w2   = (const float*)d_in[7];
    float* out = (float*)d_out;

    static bool attr_set = false;
    if (!attr_set) {
        cudaFuncSetAttribute(k_gemm_x, cudaFuncAttributeMaxDynamicSharedMemorySize,
                             GEMM_SMEM);
        attr_set = true;
    }

    k_zero<<<(PP * NN + 255) / 256, 256>>>();
    k_deg<<<(PP * EE + 255) / 256, 256>>>(src, dst);
    k_scan<<<PP, 1024>>>();
    k_fill<<<(PP * EE + 255) / 256, 256>>>(src, dst);
    k_split_h<<<(int)(((size_t)NN * CIN + 255) / 256), 256>>>(h);
    k_split_w<<<(PP * CIN * DD + 255) / 256, 256>>>(W_gc);
    k_split_w1<<<(DD * SEMH + 255) / 256, 256>>>(W1);
    k_gemm_x<<<dim3(MTILES, DD / BN, PP), 256, GEMM_SMEM>>>();
    for (int p = 0; p < PP; p++)
        k_agg<<<NN, 256>>>(b_gc, p);
    k_sem_tc<<<dim3(MTILES, 1, PP), 256>>>(b1, w2);
    k_beta<<<1, 32>>>();
    k_comb<<<(int)(((size_t)NN * DD / 4 + 255) / 256), 256>>>(out);
}

// round 11
// speedup vs baseline: 2.3761x; 1.1460x over previous
#include <cuda_runtime.h>
#include <cuda_fp16.h>
#include <cstdint>

#define NN   50000
#define EE   800000
#define PP   4
#define CIN  256
#define DD   256
#define SEMH 128

// mma tiling
#define BM 128
#define BN 128
#define BK 32
#define SA 40                    // padded smem row stride (fp16 elems) = 80B (16B-aligned)
#define MTILES ((NN + BM - 1) / BM)
#define TILE_ELEMS (BM * SA)             // fp16 elems per tile
#define TILE_BYTES (TILE_ELEMS * 2)      // 10240
#define GEMM_SMEM (2 * 3 * TILE_BYTES)   // 61440 (double buffer x 3 arrays)

// scan tiling
#define SCAN_B 1024
#define NBLK ((NN + SCAN_B - 1) / SCAN_B)   // 49

// ---------------- scratch (device globals; no allocations allowed) ----------
__device__ __half g_x[(size_t)PP * NN * DD];     // fp16 (h@W)*rsqrt(deg_out)
__device__ __half g_z[(size_t)PP * NN * DD];     // fp16 per-metapath embeddings
__device__ int   g_deg_out[PP * NN];
__device__ int   g_deg_in [PP * NN];
__device__ int   g_row_start[PP * NN];
__device__ int   g_cursor   [PP * NN];
__device__ int   g_blksum   [PP * NBLK];
__device__ int   g_csr_src[(size_t)PP * EE];
__device__ float g_s_sum[PP];
__device__ float g_beta [PP];
// fp16 split staging
__device__ __half g_h_hi[(size_t)NN * CIN];
__device__ __half g_h_lo[(size_t)NN * CIN];
__device__ __half g_wt  [(size_t)PP * DD * CIN];   // fp16(W^T): [p][n][k]
__device__ __half g_w1t_hi[(size_t)SEMH * DD];     // W1^T hi: [n][k]
__device__ __half g_w1t_lo[(size_t)SEMH * DD];     // W1^T lo

// ---------------- helpers ---------------------------------------------------
__device__ __forceinline__ void mma_f16(float c[4],
                                        uint32_t a0, uint32_t a1, uint32_t a2, uint32_t a3,
                                        uint32_t b0, uint32_t b1) {
    asm volatile(
        "mma.sync.aligned.m16n8k16.row.col.f32.f16.f16.f32 "
        "{%0,%1,%2,%3}, {%4,%5,%6,%7}, {%8,%9}, {%0,%1,%2,%3};"
        : "+f"(c[0]), "+f"(c[1]), "+f"(c[2]), "+f"(c[3])
        : "r"(a0), "r"(a1), "r"(a2), "r"(a3), "r"(b0), "r"(b1));
}
__device__ __forceinline__ uint32_t ld32(const void* p) {
    return *(const uint32_t*)p;
}
__device__ __forceinline__ uint32_t smem_u32(const void* p) {
    uint32_t a;
    asm("{ .reg .u64 t; cvta.to.shared.u64 t, %1; cvt.u32.u64 %0, t; }" : "=r"(a) : "l"(p));
    return a;
}
__device__ __forceinline__ void cp16(uint32_t sdst, const void* gsrc, int src_sz) {
    asm volatile("cp.async.cg.shared.global [%0], [%1], 16, %2;"
                 :: "r"(sdst), "l"(gsrc), "r"(src_sz) : "memory");
}
#define CP_COMMIT() asm volatile("cp.async.commit_group;" ::: "memory")
#define CP_WAIT(n)  asm volatile("cp.async.wait_group %0;" :: "n"(n) : "memory")

// ---------------- 1. zero counters ----------------
__global__ void k_zero() {
    int i = blockIdx.x * blockDim.x + threadIdx.x;
    if (i < PP * NN) { g_deg_out[i] = 0; g_deg_in[i] = 0; }
    if (i < PP) g_s_sum[i] = 0.f;
}

// ---------------- 2. degrees ----------------
__global__ void k_deg(const int* __restrict__ src, const int* __restrict__ dst) {
    int i = blockIdx.x * blockDim.x + threadIdx.x;
    if (i >= PP * EE) return;
    int p = i / EE;
    atomicAdd(&g_deg_out[p * NN + src[i]], 1);
    atomicAdd(&g_deg_in [p * NN + dst[i]], 1);
}

// ---------------- 3. full-chip 3-phase exclusive scan of deg_in -------------
// 3a: per-block local exclusive scan (warp shuffles) + block sums
__global__ __launch_bounds__(SCAN_B) void k_scan1() {
    const int p   = blockIdx.y;
    const int b   = blockIdx.x;
    const int tid = threadIdx.x;
    const int lane = tid & 31, wid = tid >> 5;
    const int i = b * SCAN_B + tid;
    int v = (i < NN) ? g_deg_in[p * NN + i] : 0;
    int x = v;
#pragma unroll
    for (int o = 1; o < 32; o <<= 1) {
        int y = __shfl_up_sync(~0u, x, o);
        if (lane >= o) x += y;
    }
    __shared__ int wsum[32];
    if (lane == 31) wsum[wid] = x;
    __syncthreads();
    if (wid == 0) {
        int s = wsum[lane];
#pragma unroll
        for (int o = 1; o < 32; o <<= 1) {
            int y = __shfl_up_sync(~0u, s, o);
            if (lane >= o) s += y;
        }
        wsum[lane] = s;   // inclusive warp sums
    }
    __syncthreads();
    int woff = (wid == 0) ? 0 : wsum[wid - 1];
    if (i < NN) g_row_start[p * NN + i] = woff + x - v;   // local exclusive
    if (tid == SCAN_B - 1) g_blksum[p * NBLK + b] = woff + x;
}

// 3b: exclusive scan of the NBLK block sums, one warp per metapath
__global__ void k_scan2() {
    int w    = threadIdx.x >> 5;
    int lane = threadIdx.x & 31;
    if (w >= PP) return;
    int base = w * NBLK;
    int carry = 0;
    for (int s = 0; s < NBLK; s += 32) {
        int idx = s + lane;
        int v = (idx < NBLK) ? g_blksum[base + idx] : 0;
        int x = v;
#pragma unroll
        for (int o = 1; o < 32; o <<= 1) {
            int y = __shfl_up_sync(~0u, x, o);
            if (lane >= o) x += y;
        }
        if (idx < NBLK) g_blksum[base + idx] = carry + x - v;  // exclusive
        carry += __shfl_sync(~0u, x, 31);
    }
}

// 3c: add block offsets, init cursor
__global__ __launch_bounds__(SCAN_B) void k_scan3() {
    const int p = blockIdx.y;
    const int b = blockIdx.x;
    const int i = b * SCAN_B + threadIdx.x;
    if (i >= NN) return;
    int rs = g_row_start[p * NN + i] + g_blksum[p * NBLK + b];
    g_row_start[p * NN + i] = rs;
    g_cursor   [p * NN + i] = rs;
}

// ---------------- 4. fill CSR (by dst) ----------------
__global__ void k_fill(const int* __restrict__ src, const int* __restrict__ dst) {
    int i = blockIdx.x * blockDim.x + threadIdx.x;
    if (i >= PP * EE) return;
    int p = i / EE;
    int d = dst[i];
    int pos = atomicAdd(&g_cursor[p * NN + d], 1);
    g_csr_src[(size_t)p * EE + pos] = src[i];
}

// ---------------- 5a. fp16 hi/lo split of h ---------------------------------
__global__ void k_split_h(const float* __restrict__ h) {
    size_t i = (size_t)blockIdx.x * blockDim.x + threadIdx.x;
    if (i >= (size_t)NN * CIN) return;
    float x = h[i];
    __half hi = __float2half_rn(x);
    __half lo = __float2half_rn(x - __half2float(hi));
    g_h_hi[i] = hi; g_h_lo[i] = lo;
}

// ---------------- 5b. fused weight prep: W_gc (fp16 ^T) + W1 (hi/lo ^T) -----
__global__ void k_split_weights(const float* __restrict__ Wg,
                                const float* __restrict__ W1) {
    int i = blockIdx.x * blockDim.x + threadIdx.x;
    if (i < PP * CIN * DD) {
        int p = i / (CIN * DD);
        int r = i % (CIN * DD);
        int k = r / DD;
        int n = r % DD;
        g_wt[((size_t)p * DD + n) * CIN + k] = __float2half_rn(Wg[i]);
    }
    int j = i - PP * CIN * DD;
    if (j >= 0 && j < DD * SEMH) {
        int k = j / SEMH;
        int n = j % SEMH;
        float x = W1[j];
        __half hi = __float2half_rn(x);
        __half lo = __float2half_rn(x - __half2float(hi));
        size_t d = (size_t)n * DD + k;
        g_w1t_hi[d] = hi; g_w1t_lo[d] = lo;
    }
}

// ---------------- 6. tensor GEMM: x = fp16((h @ W_p) * rsqrt(deg_out)) ------
__global__ __launch_bounds__(256) void k_gemm_x() {
    extern __shared__ __half smg[];
    const uint32_t sbase = smem_u32(smg);

    const int tid   = threadIdx.x;
    const int lane  = tid & 31;
    const int wid   = tid >> 5;
    const int wm    = wid & 3;
    const int wn    = wid >> 2;
    const int g     = lane >> 2;
    const int tig   = lane & 3;
    const int p     = blockIdx.z;
    const int m0    = blockIdx.x * BM;
    const int n0    = blockIdx.y * BN;

    const __half* Wt = g_wt + (size_t)p * DD * CIN;

    float c[2][8][4];
#pragma unroll
    for (int mi = 0; mi < 2; mi++)
#pragma unroll
        for (int ni = 0; ni < 8; ni++)
#pragma unroll
            for (int j = 0; j < 4; j++) c[mi][ni][j] = 0.f;

    auto issue = [&](int kch, int buf) {
        const int k0 = kch * BK;
        const uint32_t b = sbase + (uint32_t)buf * 3u * TILE_BYTES;
#pragma unroll
        for (int it = 0; it < 2; it++) {
            int idx = tid + it * 256;            // BM*(BK/8)=512 chunks
            int r  = idx >> 2;
            int cc = (idx & 3) * 8;
            uint32_t soff = (uint32_t)(r * SA + cc) * 2u;
            int sr = m0 + r;
            int ok = (sr < NN);
            size_t aoff = (size_t)(ok ? sr : 0) * CIN + k0 + cc;
            cp16(b + 0 * TILE_BYTES + soff, g_h_hi + aoff, ok ? 16 : 0);
            cp16(b + 1 * TILE_BYTES + soff, g_h_lo + aoff, ok ? 16 : 0);
            size_t boff = (size_t)(n0 + r) * CIN + k0 + cc;
            cp16(b + 2 * TILE_BYTES + soff, Wt + boff, 16);
        }
    };

    const int NK = CIN / BK;   // 8
    issue(0, 0);
    CP_COMMIT();
    for (int kc = 0; kc < NK; kc++) {
        const int buf = kc & 1;
        if (kc + 1 < NK) {
            issue(kc + 1, buf ^ 1);
            CP_COMMIT();
            CP_WAIT(1);
        } else {
            CP_WAIT(0);
        }
        __syncthreads();

        const __half* sAh = smg + (size_t)buf * 3 * TILE_ELEMS;
        const __half* sAl = sAh + TILE_ELEMS;
        const __half* sB  = sAl + TILE_ELEMS;

#pragma unroll
        for (int ks = 0; ks < BK; ks += 16) {
            const int c0 = ks + tig * 2;
            uint32_t ah[2][4], al[2][4];
#pragma unroll
            for (int mi = 0; mi < 2; mi++) {
                int r0 = wm * 32 + mi * 16 + g;
                ah[mi][0] = ld32(&sAh[r0 * SA + c0]);
                ah[mi][1] = ld32(&sAh[(r0 + 8) * SA + c0]);
                ah[mi][2] = ld32(&sAh[r0 * SA + c0 + 8]);
                ah[mi][3] = ld32(&sAh[(r0 + 8) * SA + c0 + 8]);
                al[mi][0] = ld32(&sAl[r0 * SA + c0]);
                al[mi][1] = ld32(&sAl[(r0 + 8) * SA + c0]);
                al[mi][2] = ld32(&sAl[r0 * SA + c0 + 8]);
                al[mi][3] = ld32(&sAl[(r0 + 8) * SA + c0 + 8]);
            }
#pragma unroll
            for (int ni = 0; ni < 8; ni++) {
                int nb = wn * 64 + ni * 8 + g;
                uint32_t b0 = ld32(&sB[nb * SA + c0]);
                uint32_t b1 = ld32(&sB[nb * SA + c0 + 8]);
#pragma unroll
                for (int mi = 0; mi < 2; mi++) {
                    mma_f16(c[mi][ni], ah[mi][0], ah[mi][1], ah[mi][2], ah[mi][3], b0, b1);
                    mma_f16(c[mi][ni], al[mi][0], al[mi][1], al[mi][2], al[mi][3], b0, b1);
                }
            }
        }
        __syncthreads();
    }

    // epilogue: scale by rsqrt(deg_out), store fp16
#pragma unroll
    for (int mi = 0; mi < 2; mi++) {
        int row0 = m0 + wm * 32 + mi * 16 + g;
        int row1 = row0 + 8;
        float rs0 = (row0 < NN) ? rsqrtf((float)max(g_deg_out[p * NN + row0], 1)) : 0.f;
        float rs1 = (row1 < NN) ? rsqrtf((float)max(g_deg_out[p * NN + row1], 1)) : 0.f;
#pragma unroll
        for (int ni = 0; ni < 8; ni++) {
            int col = n0 + wn * 64 + ni * 8 + tig * 2;
            if (row0 < NN) {
                __half2 v = __floats2half2_rn(c[mi][ni][0] * rs0, c[mi][ni][1] * rs0);
                *(__half2*)(g_x + ((size_t)p * NN + row0) * DD + col) = v;
            }
            if (row1 < NN) {
                __half2 v = __floats2half2_rn(c[mi][ni][2] * rs1, c[mi][ni][3] * rs1);
                *(__half2*)(g_x + ((size_t)p * NN + row1) * DD + col) = v;
            }
        }
    }
}

// ---------------- 7. aggregate over in-edges (fp16 gather, fp32 accum) ------
__global__ __launch_bounds__(256) void k_agg(const float* __restrict__ b_gc, int p) {
    const int n   = blockIdx.x;
    const int tid = threadIdx.x;
    const int grp = tid >> 6;
    const int t   = tid & 63;
    const int base  = p * NN + n;
    const int start = g_row_start[base];
    const int deg   = g_deg_in[base];
    const __half* X = g_x + (size_t)p * NN * DD;
    const int* cs   = g_csr_src + (size_t)p * EE + start;

    float4 acc = make_float4(0.f, 0.f, 0.f, 0.f);
    int e = grp;
    for (; e + 4 < deg; e += 8) {
        int s0 = cs[e], s1 = cs[e + 4];
        uint2 v0 = *(const uint2*)(X + (size_t)s0 * DD + t * 4);
        uint2 v1 = *(const uint2*)(X + (size_t)s1 * DD + t * 4);
        float2 a0 = __half22float2(*(__half2*)&v0.x);
        float2 a1 = __half22float2(*(__half2*)&v0.y);
        float2 b0 = __half22float2(*(__half2*)&v1.x);
        float2 b1 = __half22float2(*(__half2*)&v1.y);
        acc.x += a0.x + b0.x; acc.y += a0.y + b0.y;
        acc.z += a1.x + b1.x; acc.w += a1.y + b1.y;
    }
    if (e < deg) {
        int s0 = cs[e];
        uint2 v0 = *(const uint2*)(X + (size_t)s0 * DD + t * 4);
        float2 a0 = __half22float2(*(__half2*)&v0.x);
        float2 a1 = __half22float2(*(__half2*)&v0.y);
        acc.x += a0.x; acc.y += a0.y; acc.z += a1.x; acc.w += a1.y;
    }

    __shared__ float sacc[4][256];
    *(float4*)&sacc[grp][t * 4] = acc;
    __syncthreads();

    __shared__ float sval[256];
    {
        float v = sacc[0][tid] + sacc[1][tid] + sacc[2][tid] + sacc[3][tid];
        float rs = rsqrtf((float)max(deg, 1));
        sval[tid] = v * rs + b_gc[p * DD + tid];
    }
    __syncthreads();
    if (tid < 64) {
        __half2 h0 = __floats2half2_rn(sval[tid * 4 + 0], sval[tid * 4 + 1]);
        __half2 h1 = __floats2half2_rn(sval[tid * 4 + 2], sval[tid * 4 + 3]);
        uint2 pk; pk.x = *(uint32_t*)&h0; pk.y = *(uint32_t*)&h1;
        *(uint2*)(g_z + ((size_t)p * NN + n) * DD + tid * 4) = pk;
    }
}

// ---------------- 8. semantic attention via fp16 mma (cp.async pipelined) ---
// s[n,p] = tanh(z@W1 + b1).w2 ; sum over nodes -> g_s_sum[p]
__global__ __launch_bounds__(256) void k_sem_tc(const float* __restrict__ b1,
                                                const float* __restrict__ w2) {
    extern __shared__ __half sms[];
    const uint32_t sbase = smem_u32(sms);
    __shared__ float sred[128][9];
    __shared__ float sblk[128];

    const int tid  = threadIdx.x;
    const int lane = tid & 31;
    const int wid  = tid >> 5;
    const int wm   = wid & 3;
    const int wn   = wid >> 2;
    const int g    = lane >> 2;
    const int tig  = lane & 3;
    const int p    = blockIdx.z;
    const int m0   = blockIdx.x * BM;

    const __half* Z = g_z + (size_t)p * NN * DD;

    float c[2][8][4];
#pragma unroll
    for (int mi = 0; mi < 2; mi++)
#pragma unroll
        for (int ni = 0; ni < 8; ni++)
#pragma unroll
            for (int j = 0; j < 4; j++) c[mi][ni][j] = 0.f;

    auto issue = [&](int kch, int buf) {
        const int k0 = kch * BK;
        const uint32_t b = sbase + (uint32_t)buf * 3u * TILE_BYTES;
#pragma unroll
        for (int it = 0; it < 2; it++) {
            int idx = tid + it * 256;            // 512 chunks each
            int r  = idx >> 2;
            int cc = (idx & 3) * 8;
            uint32_t soff = (uint32_t)(r * SA + cc) * 2u;
            int sr = m0 + r;
            int ok = (sr < NN);
            size_t aoff = (size_t)(ok ? sr : 0) * DD + k0 + cc;
            cp16(b + 0 * TILE_BYTES + soff, Z + aoff, ok ? 16 : 0);
            size_t boff = (size_t)r * DD + k0 + cc;   // SEMH=128 rows
            cp16(b + 1 * TILE_BYTES + soff, g_w1t_hi + boff, 16);
            cp16(b + 2 * TILE_BYTES + soff, g_w1t_lo + boff, 16);
        }
    };

    const int NK = DD / BK;   // 8
    issue(0, 0);
    CP_COMMIT();
    for (int kc = 0; kc < NK; kc++) {
        const int buf = kc & 1;
        if (kc + 1 < NK) {
            issue(kc + 1, buf ^ 1);
            CP_COMMIT();
            CP_WAIT(1);
        } else {
            CP_WAIT(0);
        }
        __syncthreads();

        const __half* sA  = sms + (size_t)buf * 3 * TILE_ELEMS;
        const __half* sBh = sA + TILE_ELEMS;
        const __half* sBl = sBh + TILE_ELEMS;

#pragma unroll
        for (int ks = 0; ks < BK; ks += 16) {
            const int c0 = ks + tig * 2;
            uint32_t a[2][4];
#pragma unroll
            for (int mi = 0; mi < 2; mi++) {
                int r0 = wm * 32 + mi * 16 + g;
                a[mi][0] = ld32(&sA[r0 * SA + c0]);
                a[mi][1] = ld32(&sA[(r0 + 8) * SA + c0]);
                a[mi][2] = ld32(&sA[r0 * SA + c0 + 8]);
                a[mi][3] = ld32(&sA[(r0 + 8) * SA + c0 + 8]);
            }
#pragma unroll
            for (int ni = 0; ni < 8; ni++) {
                int nb = wn * 64 + ni * 8 + g;
                uint32_t bh0 = ld32(&sBh[nb * SA + c0]);
                uint32_t bh1 = ld32(&sBh[nb * SA + c0 + 8]);
                uint32_t bl0 = ld32(&sBl[nb * SA + c0]);
                uint32_t bl1 = ld32(&sBl[nb * SA + c0 + 8]);
#pragma unroll
                for (int mi = 0; mi < 2; mi++) {
                    mma_f16(c[mi][ni], a[mi][0], a[mi][1], a[mi][2], a[mi][3], bh0, bh1);
                    mma_f16(c[mi][ni], a[mi][0], a[mi][1], a[mi][2], a[mi][3], bl0, bl1);
                }
            }
        }
        __syncthreads();
    }

    float vrow[2][2] = {{0.f, 0.f}, {0.f, 0.f}};
#pragma unroll
    for (int ni = 0; ni < 8; ni++) {
        int col = wn * 64 + ni * 8 + tig * 2;
        float b1a = b1[col], b1b = b1[col + 1];
        float w2a = w2[col], w2b = w2[col + 1];
#pragma unroll
        for (int mi = 0; mi < 2; mi++) {
            vrow[mi][0] += tanhf(c[mi][ni][0] + b1a) * w2a + tanhf(c[mi][ni][1] + b1b) * w2b;
            vrow[mi][1] += tanhf(c[mi][ni][2] + b1a) * w2a + tanhf(c[mi][ni][3] + b1b) * w2b;
        }
    }
#pragma unroll
    for (int mi = 0; mi < 2; mi++) {
        int r0 = wm * 32 + mi * 16 + g;
        sred[r0][wn * 4 + tig]     = vrow[mi][0];
        sred[r0 + 8][wn * 4 + tig] = vrow[mi][1];
    }
    __syncthreads();
    if (tid < 128) {
        float sv = 0.f;
        if (m0 + tid < NN) {
#pragma unroll
            for (int t = 0; t < 8; t++) sv += sred[tid][t];
        }
        sblk[tid] = sv;
    }
    __syncthreads();
    for (int off = 64; off > 0; off >>= 1) {
        if (tid < off) sblk[tid] += sblk[tid + off];
        __syncthreads();
    }
    if (tid == 0) atomicAdd(&g_s_sum[p], sblk[0]);
}

// ---------------- 9. beta = softmax(mean over nodes) ------------------------
__global__ void k_beta() {
    if (threadIdx.x == 0 && blockIdx.x == 0) {
        float m[PP]; float mx = -1e30f;
        for (int p = 0; p < PP; p++) { m[p] = g_s_sum[p] / (float)NN; mx = fmaxf(mx, m[p]); }
        float se = 0.f;
        for (int p = 0; p < PP; p++) { m[p] = expf(m[p] - mx); se += m[p]; }
        for (int p = 0; p < PP; p++) g_beta[p] = m[p] / se;
    }
}

// ---------------- 10. combine: out = sum_p beta[p] * z_p (fp16 -> fp32) -----
__global__ void k_comb(float* __restrict__ out) {
    const size_t q = (size_t)NN * DD / 4;   // half4 (8B) chunks per metapath
    size_t i = (size_t)blockIdx.x * blockDim.x + threadIdx.x;
    if (i >= q) return;
    float b0 = g_beta[0], b1 = g_beta[1], b2 = g_beta[2], b3 = g_beta[3];
    const uint2* z = (const uint2*)g_z;
    uint2 u0 = z[i], u1 = z[q + i], u2 = z[2 * q + i], u3 = z[3 * q + i];
    float2 p0a = __half22float2(*(__half2*)&u0.x), p0b = __half22float2(*(__half2*)&u0.y);
    float2 p1a = __half22float2(*(__half2*)&u1.x), p1b = __half22float2(*(__half2*)&u1.y);
    float2 p2a = __half22float2(*(__half2*)&u2.x), p2b = __half22float2(*(__half2*)&u2.y);
    float2 p3a = __half22float2(*(__half2*)&u3.x), p3b = __half22float2(*(__half2*)&u3.y);
    float4 o;
    o.x = b0 * p0a.x + b1 * p1a.x + b2 * p2a.x + b3 * p3a.x;
    o.y = b0 * p0a.y + b1 * p1a.y + b2 * p2a.y + b3 * p3a.y;
    o.z = b0 * p0b.x + b1 * p1b.x + b2 * p2b.x + b3 * p3b.x;
    o.w = b0 * p0b.y + b1 * p1b.y + b2 * p2b.y + b3 * p3b.y;
    ((float4*)out)[i] = o;
}

// ---------------- launch ----------------------------------------------------
extern "C" void kernel_launch(void* const* d_in, const int* in_sizes, int n_in,
                              void* d_out, int out_size) {
    const float* h    = (const float*)d_in[0];
    const int*   src  = (const int*)  d_in[1];
    const int*   dst  = (const int*)  d_in[2];
    const float* W_gc = (const float*)d_in[3];
    const float* b_gc = (const float*)d_in[4];
    const float* W1   = (const float*)d_in[5];
    const float* b1   = (const float*)d_in[6];
    const float* w2   = (const float*)d_in[7];
    float* out = (float*)d_out;

    static bool attr_set = false;
    if (!attr_set) {
        cudaFuncSetAttribute(k_gemm_x, cudaFuncAttributeMaxDynamicSharedMemorySize,
                             GEMM_SMEM);
        cudaFuncSetAttribute(k_sem_tc, cudaFuncAttributeMaxDynamicSharedMemorySize,
                             GEMM_SMEM);
        attr_set = true;
    }

    k_zero<<<(PP * NN + 255) / 256, 256>>>();
    k_deg<<<(PP * EE + 255) / 256, 256>>>(src, dst);
    k_scan1<<<dim3(NBLK, PP), SCAN_B>>>();
    k_scan2<<<1, PP * 32>>>();
    k_scan3<<<dim3(NBLK, PP), SCAN_B>>>();
    k_fill<<<(PP * EE + 255) / 256, 256>>>(src, dst);
    k_split_h<<<(int)(((size_t)NN * CIN + 255) / 256), 256>>>(h);
    k_split_weights<<<(PP * CIN * DD + DD * SEMH + 255) / 256, 256>>>(W_gc, W1);
    k_gemm_x<<<dim3(MTILES, DD / BN, PP), 256, GEMM_SMEM>>>();
    for (int p = 0; p < PP; p++)
        k_agg<<<NN, 256>>>(b_gc, p);
    k_sem_tc<<<dim3(MTILES, 1, PP), 256, GEMM_SMEM>>>(b1, w2);
    k_beta<<<1, 32>>>();
    k_comb<<<(int)(((size_t)NN * DD / 4 + 255) / 256), 256>>>(out);
}

// round 12
// speedup vs baseline: 3.0156x; 1.2691x over previous
#include <cuda_runtime.h>
#include <cuda_fp16.h>
#include <cstdint>

#define NN   50000
#define EE   800000
#define PP   4
#define CIN  256
#define DD   256
#define SEMH 128

// mma tiling
#define BM 128
#define BN 128
#define BK 32
#define SA 40                    // padded smem row stride (fp16 elems) = 80B (16B-aligned)
#define MTILES ((NN + BM - 1) / BM)
#define TILE_ELEMS (BM * SA)             // fp16 elems per tile
#define TILE_BYTES (TILE_ELEMS * 2)      // 10240
#define GEMM_SMEM (2 * 3 * TILE_BYTES)   // 61440 (double buffer x 3 arrays)

// scan tiling
#define SCAN_B 1024
#define NBLK ((NN + SCAN_B - 1) / SCAN_B)   // 49

// ---------------- scratch (device globals; no allocations allowed) ----------
__device__ __half g_x[(size_t)PP * NN * DD];     // fp16 (h@W)*rsqrt(deg_out)
__device__ __half g_z[(size_t)PP * NN * DD];     // fp16 per-metapath embeddings
__device__ int   g_deg_out[PP * NN];
__device__ int   g_deg_in [PP * NN];
__device__ int   g_row_start[PP * NN];
__device__ int   g_cursor   [PP * NN];
__device__ int   g_blksum   [PP * NBLK];
__device__ int   g_csr_src[(size_t)PP * EE];
__device__ float g_s_sum[PP];
__device__ float g_beta [PP];
// fp16 split staging
__device__ __half g_h_hi[(size_t)NN * CIN];
__device__ __half g_h_lo[(size_t)NN * CIN];
__device__ __half g_wt  [(size_t)PP * DD * CIN];   // fp16(W^T): [p][n][k]
__device__ __half g_w1t_hi[(size_t)SEMH * DD];     // W1^T hi: [n][k]
__device__ __half g_w1t_lo[(size_t)SEMH * DD];     // W1^T lo

// ---------------- helpers ---------------------------------------------------
__device__ __forceinline__ void mma_f16(float c[4],
                                        uint32_t a0, uint32_t a1, uint32_t a2, uint32_t a3,
                                        uint32_t b0, uint32_t b1) {
    asm volatile(
        "mma.sync.aligned.m16n8k16.row.col.f32.f16.f16.f32 "
        "{%0,%1,%2,%3}, {%4,%5,%6,%7}, {%8,%9}, {%0,%1,%2,%3};"
        : "+f"(c[0]), "+f"(c[1]), "+f"(c[2]), "+f"(c[3])
        : "r"(a0), "r"(a1), "r"(a2), "r"(a3), "r"(b0), "r"(b1));
}
__device__ __forceinline__ uint32_t ld32(const void* p) {
    return *(const uint32_t*)p;
}
__device__ __forceinline__ uint32_t smem_u32(const void* p) {
    uint32_t a;
    asm("{ .reg .u64 t; cvta.to.shared.u64 t, %1; cvt.u32.u64 %0, t; }" : "=r"(a) : "l"(p));
    return a;
}
__device__ __forceinline__ void cp16(uint32_t sdst, const void* gsrc, int src_sz) {
    asm volatile("cp.async.cg.shared.global [%0], [%1], 16, %2;"
                 :: "r"(sdst), "l"(gsrc), "r"(src_sz) : "memory");
}
#define CP_COMMIT() asm volatile("cp.async.commit_group;" ::: "memory")
#define CP_WAIT(n)  asm volatile("cp.async.wait_group %0;" :: "n"(n) : "memory")

// ---------------- 1. zero counters ----------------
__global__ void k_zero() {
    int i = blockIdx.x * blockDim.x + threadIdx.x;
    if (i < PP * NN) { g_deg_out[i] = 0; g_deg_in[i] = 0; }
    if (i < PP) g_s_sum[i] = 0.f;
}

// ---------------- 2. degrees ----------------
__global__ void k_deg(const int* __restrict__ src, const int* __restrict__ dst) {
    int i = blockIdx.x * blockDim.x + threadIdx.x;
    if (i >= PP * EE) return;
    int p = i / EE;
    atomicAdd(&g_deg_out[p * NN + src[i]], 1);
    atomicAdd(&g_deg_in [p * NN + dst[i]], 1);
}

// ---------------- 3. full-chip 3-phase exclusive scan of deg_in -------------
__global__ __launch_bounds__(SCAN_B) void k_scan1() {
    const int p   = blockIdx.y;
    const int b   = blockIdx.x;
    const int tid = threadIdx.x;
    const int lane = tid & 31, wid = tid >> 5;
    const int i = b * SCAN_B + tid;
    int v = (i < NN) ? g_deg_in[p * NN + i] : 0;
    int x = v;
#pragma unroll
    for (int o = 1; o < 32; o <<= 1) {
        int y = __shfl_up_sync(~0u, x, o);
        if (lane >= o) x += y;
    }
    __shared__ int wsum[32];
    if (lane == 31) wsum[wid] = x;
    __syncthreads();
    if (wid == 0) {
        int s = wsum[lane];
#pragma unroll
        for (int o = 1; o < 32; o <<= 1) {
            int y = __shfl_up_sync(~0u, s, o);
            if (lane >= o) s += y;
        }
        wsum[lane] = s;
    }
    __syncthreads();
    int woff = (wid == 0) ? 0 : wsum[wid - 1];
    if (i < NN) g_row_start[p * NN + i] = woff + x - v;
    if (tid == SCAN_B - 1) g_blksum[p * NBLK + b] = woff + x;
}

__global__ void k_scan2() {
    int w    = threadIdx.x >> 5;
    int lane = threadIdx.x & 31;
    if (w >= PP) return;
    int base = w * NBLK;
    int carry = 0;
    for (int s = 0; s < NBLK; s += 32) {
        int idx = s + lane;
        int v = (idx < NBLK) ? g_blksum[base + idx] : 0;
        int x = v;
#pragma unroll
        for (int o = 1; o < 32; o <<= 1) {
            int y = __shfl_up_sync(~0u, x, o);
            if (lane >= o) x += y;
        }
        if (idx < NBLK) g_blksum[base + idx] = carry + x - v;
        carry += __shfl_sync(~0u, x, 31);
    }
}

__global__ __launch_bounds__(SCAN_B) void k_scan3() {
    const int p = blockIdx.y;
    const int b = blockIdx.x;
    const int i = b * SCAN_B + threadIdx.x;
    if (i >= NN) return;
    int rs = g_row_start[p * NN + i] + g_blksum[p * NBLK + b];
    g_row_start[p * NN + i] = rs;
    g_cursor   [p * NN + i] = rs;
}

// ---------------- 4. fill CSR (by dst) ----------------
__global__ void k_fill(const int* __restrict__ src, const int* __restrict__ dst) {
    int i = blockIdx.x * blockDim.x + threadIdx.x;
    if (i >= PP * EE) return;
    int p = i / EE;
    int d = dst[i];
    int pos = atomicAdd(&g_cursor[p * NN + d], 1);
    g_csr_src[(size_t)p * EE + pos] = src[i];
}

// ---------------- 5a. fp16 hi/lo split of h ---------------------------------
__global__ void k_split_h(const float* __restrict__ h) {
    size_t i = (size_t)blockIdx.x * blockDim.x + threadIdx.x;
    if (i >= (size_t)NN * CIN) return;
    float x = h[i];
    __half hi = __float2half_rn(x);
    __half lo = __float2half_rn(x - __half2float(hi));
    g_h_hi[i] = hi; g_h_lo[i] = lo;
}

// ---------------- 5b. fused weight prep -------------------------------------
__global__ void k_split_weights(const float* __restrict__ Wg,
                                const float* __restrict__ W1) {
    int i = blockIdx.x * blockDim.x + threadIdx.x;
    if (i < PP * CIN * DD) {
        int p = i / (CIN * DD);
        int r = i % (CIN * DD);
        int k = r / DD;
        int n = r % DD;
        g_wt[((size_t)p * DD + n) * CIN + k] = __float2half_rn(Wg[i]);
    }
    int j = i - PP * CIN * DD;
    if (j >= 0 && j < DD * SEMH) {
        int k = j / SEMH;
        int n = j % SEMH;
        float x = W1[j];
        __half hi = __float2half_rn(x);
        __half lo = __float2half_rn(x - __half2float(hi));
        size_t d = (size_t)n * DD + k;
        g_w1t_hi[d] = hi; g_w1t_lo[d] = lo;
    }
}

// ---------------- 6. tensor GEMM: x_p = fp16((h @ W_p) * rsqrt(deg_out)) ----
// grid (MTILES, DD/BN) for ONE metapath p.
__global__ __launch_bounds__(256) void k_gemm_x(int p) {
    extern __shared__ __half smg[];
    const uint32_t sbase = smem_u32(smg);

    const int tid   = threadIdx.x;
    const int lane  = tid & 31;
    const int wid   = tid >> 5;
    const int wm    = wid & 3;
    const int wn    = wid >> 2;
    const int g     = lane >> 2;
    const int tig   = lane & 3;
    const int m0    = blockIdx.x * BM;
    const int n0    = blockIdx.y * BN;

    const __half* Wt = g_wt + (size_t)p * DD * CIN;

    float c[2][8][4];
#pragma unroll
    for (int mi = 0; mi < 2; mi++)
#pragma unroll
        for (int ni = 0; ni < 8; ni++)
#pragma unroll
            for (int j = 0; j < 4; j++) c[mi][ni][j] = 0.f;

    auto issue = [&](int kch, int buf) {
        const int k0 = kch * BK;
        const uint32_t b = sbase + (uint32_t)buf * 3u * TILE_BYTES;
#pragma unroll
        for (int it = 0; it < 2; it++) {
            int idx = tid + it * 256;
            int r  = idx >> 2;
            int cc = (idx & 3) * 8;
            uint32_t soff = (uint32_t)(r * SA + cc) * 2u;
            int sr = m0 + r;
            int ok = (sr < NN);
            size_t aoff = (size_t)(ok ? sr : 0) * CIN + k0 + cc;
            cp16(b + 0 * TILE_BYTES + soff, g_h_hi + aoff, ok ? 16 : 0);
            cp16(b + 1 * TILE_BYTES + soff, g_h_lo + aoff, ok ? 16 : 0);
            size_t boff = (size_t)(n0 + r) * CIN + k0 + cc;
            cp16(b + 2 * TILE_BYTES + soff, Wt + boff, 16);
        }
    };

    const int NK = CIN / BK;   // 8
    issue(0, 0);
    CP_COMMIT();
    for (int kc = 0; kc < NK; kc++) {
        const int buf = kc & 1;
        if (kc + 1 < NK) {
            issue(kc + 1, buf ^ 1);
            CP_COMMIT();
            CP_WAIT(1);
        } else {
            CP_WAIT(0);
        }
        __syncthreads();

        const __half* sAh = smg + (size_t)buf * 3 * TILE_ELEMS;
        const __half* sAl = sAh + TILE_ELEMS;
        const __half* sB  = sAl + TILE_ELEMS;

#pragma unroll
        for (int ks = 0; ks < BK; ks += 16) {
            const int c0 = ks + tig * 2;
            uint32_t ah[2][4], al[2][4];
#pragma unroll
            for (int mi = 0; mi < 2; mi++) {
                int r0 = wm * 32 + mi * 16 + g;
                ah[mi][0] = ld32(&sAh[r0 * SA + c0]);
                ah[mi][1] = ld32(&sAh[(r0 + 8) * SA + c0]);
                ah[mi][2] = ld32(&sAh[r0 * SA + c0 + 8]);
                ah[mi][3] = ld32(&sAh[(r0 + 8) * SA + c0 + 8]);
                al[mi][0] = ld32(&sAl[r0 * SA + c0]);
                al[mi][1] = ld32(&sAl[(r0 + 8) * SA + c0]);
                al[mi][2] = ld32(&sAl[r0 * SA + c0 + 8]);
                al[mi][3] = ld32(&sAl[(r0 + 8) * SA + c0 + 8]);
            }
#pragma unroll
            for (int ni = 0; ni < 8; ni++) {
                int nb = wn * 64 + ni * 8 + g;
                uint32_t b0 = ld32(&sB[nb * SA + c0]);
                uint32_t b1 = ld32(&sB[nb * SA + c0 + 8]);
#pragma unroll
                for (int mi = 0; mi < 2; mi++) {
                    mma_f16(c[mi][ni], ah[mi][0], ah[mi][1], ah[mi][2], ah[mi][3], b0, b1);
                    mma_f16(c[mi][ni], al[mi][0], al[mi][1], al[mi][2], al[mi][3], b0, b1);
                }
            }
        }
        __syncthreads();
    }

#pragma unroll
    for (int mi = 0; mi < 2; mi++) {
        int row0 = m0 + wm * 32 + mi * 16 + g;
        int row1 = row0 + 8;
        float rs0 = (row0 < NN) ? rsqrtf((float)max(g_deg_out[p * NN + row0], 1)) : 0.f;
        float rs1 = (row1 < NN) ? rsqrtf((float)max(g_deg_out[p * NN + row1], 1)) : 0.f;
#pragma unroll
        for (int ni = 0; ni < 8; ni++) {
            int col = n0 + wn * 64 + ni * 8 + tig * 2;
            if (row0 < NN) {
                __half2 v = __floats2half2_rn(c[mi][ni][0] * rs0, c[mi][ni][1] * rs0);
                *(__half2*)(g_x + ((size_t)p * NN + row0) * DD + col) = v;
            }
            if (row1 < NN) {
                __half2 v = __floats2half2_rn(c[mi][ni][2] * rs1, c[mi][ni][3] * rs1);
                *(__half2*)(g_x + ((size_t)p * NN + row1) * DD + col) = v;
            }
        }
    }
}

// ---------------- 7. aggregate: warp-per-node, lane = 8 dims (16B) ----------
__global__ __launch_bounds__(256) void k_agg(const float* __restrict__ b_gc, int p) {
    const int warp = threadIdx.x >> 5;
    const int lane = threadIdx.x & 31;
    const int n = blockIdx.x * 8 + warp;
    if (n >= NN) return;
    const int base  = p * NN + n;
    const int start = g_row_start[base];
    const int deg   = g_deg_in[base];
    const __half* X = g_x + (size_t)p * NN * DD;
    const int* cs   = g_csr_src + (size_t)p * EE + start;
    const int d0    = lane * 8;

    float acc[8] = {};
    int e = 0;
    for (; e + 4 <= deg; e += 4) {
        int s0 = cs[e], s1 = cs[e + 1], s2 = cs[e + 2], s3 = cs[e + 3];
        uint4 v0 = *(const uint4*)(X + (size_t)s0 * DD + d0);
        uint4 v1 = *(const uint4*)(X + (size_t)s1 * DD + d0);
        uint4 v2 = *(const uint4*)(X + (size_t)s2 * DD + d0);
        uint4 v3 = *(const uint4*)(X + (size_t)s3 * DD + d0);
#pragma unroll
        for (int q = 0; q < 4; q++) {
            float2 f0 = __half22float2(((__half2*)&v0)[q]);
            float2 f1 = __half22float2(((__half2*)&v1)[q]);
            float2 f2 = __half22float2(((__half2*)&v2)[q]);
            float2 f3 = __half22float2(((__half2*)&v3)[q]);
            acc[q * 2 + 0] += (f0.x + f1.x) + (f2.x + f3.x);
            acc[q * 2 + 1] += (f0.y + f1.y) + (f2.y + f3.y);
        }
    }
    for (; e < deg; e++) {
        uint4 v0 = *(const uint4*)(X + (size_t)cs[e] * DD + d0);
#pragma unroll
        for (int q = 0; q < 4; q++) {
            float2 f0 = __half22float2(((__half2*)&v0)[q]);
            acc[q * 2 + 0] += f0.x;
            acc[q * 2 + 1] += f0.y;
        }
    }

    float rs = rsqrtf((float)max(deg, 1));
    const float4 bA = *(const float4*)(b_gc + p * DD + d0);
    const float4 bB = *(const float4*)(b_gc + p * DD + d0 + 4);
    __half2 h0 = __floats2half2_rn(acc[0] * rs + bA.x, acc[1] * rs + bA.y);
    __half2 h1 = __floats2half2_rn(acc[2] * rs + bA.z, acc[3] * rs + bA.w);
    __half2 h2 = __floats2half2_rn(acc[4] * rs + bB.x, acc[5] * rs + bB.y);
    __half2 h3 = __floats2half2_rn(acc[6] * rs + bB.z, acc[7] * rs + bB.w);
    uint4 pk;
    pk.x = *(uint32_t*)&h0; pk.y = *(uint32_t*)&h1;
    pk.z = *(uint32_t*)&h2; pk.w = *(uint32_t*)&h3;
    *(uint4*)(g_z + ((size_t)p * NN + n) * DD + d0) = pk;
}

// ---------------- 8. semantic attention via fp16 mma (per-p, pipelined) -----
__global__ __launch_bounds__(256) void k_sem_tc(int p,
                                               const float* __restrict__ b1,
                                               const float* __restrict__ w2) {
    extern __shared__ __half sms[];
    const uint32_t sbase = smem_u32(sms);
    __shared__ float sred[128][9];
    __shared__ float sblk[128];

    const int tid  = threadIdx.x;
    const int lane = tid & 31;
    const int wid  = tid >> 5;
    const int wm   = wid & 3;
    const int wn   = wid >> 2;
    const int g    = lane >> 2;
    const int tig  = lane & 3;
    const int m0   = blockIdx.x * BM;

    const __half* Z = g_z + (size_t)p * NN * DD;

    float c[2][8][4];
#pragma unroll
    for (int mi = 0; mi < 2; mi++)
#pragma unroll
        for (int ni = 0; ni < 8; ni++)
#pragma unroll
            for (int j = 0; j < 4; j++) c[mi][ni][j] = 0.f;

    auto issue = [&](int kch, int buf) {
        const int k0 = kch * BK;
        const uint32_t b = sbase + (uint32_t)buf * 3u * TILE_BYTES;
#pragma unroll
        for (int it = 0; it < 2; it++) {
            int idx = tid + it * 256;
            int r  = idx >> 2;
            int cc = (idx & 3) * 8;
            uint32_t soff = (uint32_t)(r * SA + cc) * 2u;
            int sr = m0 + r;
            int ok = (sr < NN);
            size_t aoff = (size_t)(ok ? sr : 0) * DD + k0 + cc;
            cp16(b + 0 * TILE_BYTES + soff, Z + aoff, ok ? 16 : 0);
            size_t boff = (size_t)r * DD + k0 + cc;
            cp16(b + 1 * TILE_BYTES + soff, g_w1t_hi + boff, 16);
            cp16(b + 2 * TILE_BYTES + soff, g_w1t_lo + boff, 16);
        }
    };

    const int NK = DD / BK;   // 8
    issue(0, 0);
    CP_COMMIT();
    for (int kc = 0; kc < NK; kc++) {
        const int buf = kc & 1;
        if (kc + 1 < NK) {
            issue(kc + 1, buf ^ 1);
            CP_COMMIT();
            CP_WAIT(1);
        } else {
            CP_WAIT(0);
        }
        __syncthreads();

        const __half* sA  = sms + (size_t)buf * 3 * TILE_ELEMS;
        const __half* sBh = sA + TILE_ELEMS;
        const __half* sBl = sBh + TILE_ELEMS;

#pragma unroll
        for (int ks = 0; ks < BK; ks += 16) {
            const int c0 = ks + tig * 2;
            uint32_t a[2][4];
#pragma unroll
            for (int mi = 0; mi < 2; mi++) {
                int r0 = wm * 32 + mi * 16 + g;
                a[mi][0] = ld32(&sA[r0 * SA + c0]);
                a[mi][1] = ld32(&sA[(r0 + 8) * SA + c0]);
                a[mi][2] = ld32(&sA[r0 * SA + c0 + 8]);
                a[mi][3] = ld32(&sA[(r0 + 8) * SA + c0 + 8]);
            }
#pragma unroll
            for (int ni = 0; ni < 8; ni++) {
                int nb = wn * 64 + ni * 8 + g;
                uint32_t bh0 = ld32(&sBh[nb * SA + c0]);
                uint32_t bh1 = ld32(&sBh[nb * SA + c0 + 8]);
                uint32_t bl0 = ld32(&sBl[nb * SA + c0]);
                uint32_t bl1 = ld32(&sBl[nb * SA + c0 + 8]);
#pragma unroll
                for (int mi = 0; mi < 2; mi++) {
                    mma_f16(c[mi][ni], a[mi][0], a[mi][1], a[mi][2], a[mi][3], bh0, bh1);
                    mma_f16(c[mi][ni], a[mi][0], a[mi][1], a[mi][2], a[mi][3], bl0, bl1);
                }
            }
        }
        __syncthreads();
    }

    float vrow[2][2] = {{0.f, 0.f}, {0.f, 0.f}};
#pragma unroll
    for (int ni = 0; ni < 8; ni++) {
        int col = wn * 64 + ni * 8 + tig * 2;
        float b1a = b1[col], b1b = b1[col + 1];
        float w2a = w2[col], w2b = w2[col + 1];
#pragma unroll
        for (int mi = 0; mi < 2; mi++) {
            vrow[mi][0] += tanhf(c[mi][ni][0] + b1a) * w2a + tanhf(c[mi][ni][1] + b1b) * w2b;
            vrow[mi][1] += tanhf(c[mi][ni][2] + b1a) * w2a + tanhf(c[mi][ni][3] + b1b) * w2b;
        }
    }
#pragma unroll
    for (int mi = 0; mi < 2; mi++) {
        int r0 = wm * 32 + mi * 16 + g;
        sred[r0][wn * 4 + tig]     = vrow[mi][0];
        sred[r0 + 8][wn * 4 + tig] = vrow[mi][1];
    }
    __syncthreads();
    if (tid < 128) {
        float sv = 0.f;
        if (m0 + tid < NN) {
#pragma unroll
            for (int t = 0; t < 8; t++) sv += sred[tid][t];
        }
        sblk[tid] = sv;
    }
    __syncthreads();
    for (int off = 64; off > 0; off >>= 1) {
        if (tid < off) sblk[tid] += sblk[tid + off];
        __syncthreads();
    }
    if (tid == 0) atomicAdd(&g_s_sum[p], sblk[0]);
}

// ---------------- 9. beta = softmax(mean over nodes) ------------------------
__global__ void k_beta() {
    if (threadIdx.x == 0 && blockIdx.x == 0) {
        float m[PP]; float mx = -1e30f;
        for (int p = 0; p < PP; p++) { m[p] = g_s_sum[p] / (float)NN; mx = fmaxf(mx, m[p]); }
        float se = 0.f;
        for (int p = 0; p < PP; p++) { m[p] = expf(m[p] - mx); se += m[p]; }
        for (int p = 0; p < PP; p++) g_beta[p] = m[p] / se;
    }
}

// ---------------- 10. combine: out = sum_p beta[p] * z_p (fp16 -> fp32) -----
__global__ void k_comb(float* __restrict__ out) {
    const size_t q = (size_t)NN * DD / 4;
    size_t i = (size_t)blockIdx.x * blockDim.x + threadIdx.x;
    if (i >= q) return;
    float b0 = g_beta[0], b1 = g_beta[1], b2 = g_beta[2], b3 = g_beta[3];
    const uint2* z = (const uint2*)g_z;
    uint2 u0 = z[i], u1 = z[q + i], u2 = z[2 * q + i], u3 = z[3 * q + i];
    float2 p0a = __half22float2(*(__half2*)&u0.x), p0b = __half22float2(*(__half2*)&u0.y);
    float2 p1a = __half22float2(*(__half2*)&u1.x), p1b = __half22float2(*(__half2*)&u1.y);
    float2 p2a = __half22float2(*(__half2*)&u2.x), p2b = __half22float2(*(__half2*)&u2.y);
    float2 p3a = __half22float2(*(__half2*)&u3.x), p3b = __half22float2(*(__half2*)&u3.y);
    float4 o;
    o.x = b0 * p0a.x + b1 * p1a.x + b2 * p2a.x + b3 * p3a.x;
    o.y = b0 * p0a.y + b1 * p1a.y + b2 * p2a.y + b3 * p3a.y;
    o.z = b0 * p0b.x + b1 * p1b.x + b2 * p2b.x + b3 * p3b.x;
    o.w = b0 * p0b.y + b1 * p1b.y + b2 * p2b.y + b3 * p3b.y;
    ((float4*)out)[i] = o;
}

// ---------------- launch ----------------------------------------------------
extern "C" void kernel_launch(void* const* d_in, const int* in_sizes, int n_in,
                              void* d_out, int out_size) {
    const float* h    = (const float*)d_in[0];
    const int*   src  = (const int*)  d_in[1];
    const int*   dst  = (const int*)  d_in[2];
    const float* W_gc = (const float*)d_in[3];
    const float* b_gc = (const float*)d_in[4];
    const float* W1   = (const float*)d_in[5];
    const float* b1   = (const float*)d_in[6];
    const float* w2   = (const float*)d_in[7];
    float* out = (float*)d_out;

    static cudaStream_t s1 = nullptr;
    static cudaEvent_t ev0 = nullptr, evDeg = nullptr, evCsr = nullptr;
    if (!s1) {
        cudaStreamCreateWithFlags(&s1, cudaStreamNonBlocking);
        cudaEventCreateWithFlags(&ev0,   cudaEventDisableTiming);
        cudaEventCreateWithFlags(&evDeg, cudaEventDisableTiming);
        cudaEventCreateWithFlags(&evCsr, cudaEventDisableTiming);
        cudaFuncSetAttribute(k_gemm_x, cudaFuncAttributeMaxDynamicSharedMemorySize,
                             GEMM_SMEM);
        cudaFuncSetAttribute(k_sem_tc, cudaFuncAttributeMaxDynamicSharedMemorySize,
                             GEMM_SMEM);
    }

    // main stream (0): zero, then fork CSR chain to s1
    k_zero<<<(PP * NN + 255) / 256, 256>>>();
    cudaEventRecord(ev0, 0);
    cudaStreamWaitEvent(s1, ev0, 0);

    // s1: degree + scan + CSR fill
    k_deg<<<(PP * EE + 255) / 256, 256, 0, s1>>>(src, dst);
    cudaEventRecord(evDeg, s1);
    k_scan1<<<dim3(NBLK, PP), SCAN_B, 0, s1>>>();
    k_scan2<<<1, PP * 32, 0, s1>>>();
    k_scan3<<<dim3(NBLK, PP), SCAN_B, 0, s1>>>();
    k_fill<<<(PP * EE + 255) / 256, 256, 0, s1>>>(src, dst);
    cudaEventRecord(evCsr, s1);

    // stream 0 (overlapped): input/weight prep
    k_split_h<<<(int)(((size_t)NN * CIN + 255) / 256), 256>>>(h);
    k_split_weights<<<(PP * CIN * DD + DD * SEMH + 255) / 256, 256>>>(W_gc, W1);

    // gemm needs deg_out only
    cudaStreamWaitEvent(0, evDeg, 0);
    k_gemm_x<<<dim3(MTILES, DD / BN), 256, GEMM_SMEM>>>(0);
    // agg needs the full CSR
    cudaStreamWaitEvent(0, evCsr, 0);
    k_agg<<<(NN + 7) / 8, 256>>>(b_gc, 0);
    k_sem_tc<<<MTILES, 256, GEMM_SMEM>>>(0, b1, w2);
    for (int p = 1; p < PP; p++) {
        k_gemm_x<<<dim3(MTILES, DD / BN), 256, GEMM_SMEM>>>(p);
        k_agg<<<(NN + 7) / 8, 256>>>(b_gc, p);
        k_sem_tc<<<MTILES, 256, GEMM_SMEM>>>(p, b1, w2);
    }
    k_beta<<<1, 32>>>();
    k_comb<<<(int)(((size_t)NN * DD / 4 + 255) / 256), 256>>>(out);
}

// round 13
// speedup vs baseline: 3.5462x; 1.1759x over previous
#include <cuda_runtime.h>
#include <cuda_fp16.h>
#include <cstdint>

#define NN   50000
#define EE   800000
#define PP   4
#define CIN  256
#define DD   256
#define SEMH 128

// mma tiling
#define BM 128
#define BN 128
#define BK 32
#define SA 40                    // padded smem row stride (fp16 elems) = 80B (16B-aligned)
#define MTILES ((NN + BM - 1) / BM)
#define TILE_ELEMS (BM * SA)             // fp16 elems per tile
#define TILE_BYTES (TILE_ELEMS * 2)      // 10240
#define GEMM_SMEM (2 * 3 * TILE_BYTES)   // 61440 (double buffer x 3 arrays)

// scan tiling
#define SCAN_B 1024
#define NBLK ((NN + SCAN_B - 1) / SCAN_B)   // 49

// ---------------- scratch (device globals; no allocations allowed) ----------
__device__ __half g_x[(size_t)PP * NN * DD];     // fp16 (h@W)*rsqrt(deg_out)
__device__ __half g_z[(size_t)PP * NN * DD];     // fp16 per-metapath embeddings
__device__ int   g_deg_out[PP * NN];
__device__ int   g_deg_in [PP * NN];
__device__ int   g_row_start[PP * NN];
__device__ int   g_cursor   [PP * NN];
__device__ int   g_blksum   [PP * NBLK];
__device__ int   g_csr_src[(size_t)PP * EE];
__device__ float g_s_sum[PP];
__device__ float g_beta [PP];
// fp16 split staging
__device__ __half g_h_hi[(size_t)NN * CIN];
__device__ __half g_h_lo[(size_t)NN * CIN];
__device__ __half g_wt  [(size_t)PP * DD * CIN];   // fp16(W^T): [p][n][k]
__device__ __half g_w1t_hi[(size_t)SEMH * DD];     // W1^T hi: [n][k]
__device__ __half g_w1t_lo[(size_t)SEMH * DD];     // W1^T lo

// ---------------- helpers ---------------------------------------------------
__device__ __forceinline__ void mma_f16(float c[4],
                                        uint32_t a0, uint32_t a1, uint32_t a2, uint32_t a3,
                                        uint32_t b0, uint32_t b1) {
    asm volatile(
        "mma.sync.aligned.m16n8k16.row.col.f32.f16.f16.f32 "
        "{%0,%1,%2,%3}, {%4,%5,%6,%7}, {%8,%9}, {%0,%1,%2,%3};"
        : "+f"(c[0]), "+f"(c[1]), "+f"(c[2]), "+f"(c[3])
        : "r"(a0), "r"(a1), "r"(a2), "r"(a3), "r"(b0), "r"(b1));
}
__device__ __forceinline__ uint32_t ld32(const void* p) {
    return *(const uint32_t*)p;
}
__device__ __forceinline__ uint32_t smem_u32(const void* p) {
    uint32_t a;
    asm("{ .reg .u64 t; cvta.to.shared.u64 t, %1; cvt.u32.u64 %0, t; }" : "=r"(a) : "l"(p));
    return a;
}
__device__ __forceinline__ void cp16(uint32_t sdst, const void* gsrc, int src_sz) {
    asm volatile("cp.async.cg.shared.global [%0], [%1], 16, %2;"
                 :: "r"(sdst), "l"(gsrc), "r"(src_sz) : "memory");
}
#define CP_COMMIT() asm volatile("cp.async.commit_group;" ::: "memory")
#define CP_WAIT(n)  asm volatile("cp.async.wait_group %0;" :: "n"(n) : "memory")

// ---------------- 1. zero counters ----------------
__global__ void k_zero() {
    int i = blockIdx.x * blockDim.x + threadIdx.x;
    if (i < PP * NN) { g_deg_out[i] = 0; g_deg_in[i] = 0; }
    if (i < PP) g_s_sum[i] = 0.f;
}

// ---------------- 2. degrees ----------------
__global__ void k_deg(const int* __restrict__ src, const int* __restrict__ dst) {
    int i = blockIdx.x * blockDim.x + threadIdx.x;
    if (i >= PP * EE) return;
    int p = i / EE;
    atomicAdd(&g_deg_out[p * NN + src[i]], 1);
    atomicAdd(&g_deg_in [p * NN + dst[i]], 1);
}

// ---------------- 3. full-chip 3-phase exclusive scan of deg_in -------------
__global__ __launch_bounds__(SCAN_B) void k_scan1() {
    const int p   = blockIdx.y;
    const int b   = blockIdx.x;
    const int tid = threadIdx.x;
    const int lane = tid & 31, wid = tid >> 5;
    const int i = b * SCAN_B + tid;
    int v = (i < NN) ? g_deg_in[p * NN + i] : 0;
    int x = v;
#pragma unroll
    for (int o = 1; o < 32; o <<= 1) {
        int y = __shfl_up_sync(~0u, x, o);
        if (lane >= o) x += y;
    }
    __shared__ int wsum[32];
    if (lane == 31) wsum[wid] = x;
    __syncthreads();
    if (wid == 0) {
        int s = wsum[lane];
#pragma unroll
        for (int o = 1; o < 32; o <<= 1) {
            int y = __shfl_up_sync(~0u, s, o);
            if (lane >= o) s += y;
        }
        wsum[lane] = s;
    }
    __syncthreads();
    int woff = (wid == 0) ? 0 : wsum[wid - 1];
    if (i < NN) g_row_start[p * NN + i] = woff + x - v;
    if (tid == SCAN_B - 1) g_blksum[p * NBLK + b] = woff + x;
}

__global__ void k_scan2() {
    int w    = threadIdx.x >> 5;
    int lane = threadIdx.x & 31;
    if (w >= PP) return;
    int base = w * NBLK;
    int carry = 0;
    for (int s = 0; s < NBLK; s += 32) {
        int idx = s + lane;
        int v = (idx < NBLK) ? g_blksum[base + idx] : 0;
        int x = v;
#pragma unroll
        for (int o = 1; o < 32; o <<= 1) {
            int y = __shfl_up_sync(~0u, x, o);
            if (lane >= o) x += y;
        }
        if (idx < NBLK) g_blksum[base + idx] = carry + x - v;
        carry += __shfl_sync(~0u, x, 31);
    }
}

__global__ __launch_bounds__(SCAN_B) void k_scan3() {
    const int p = blockIdx.y;
    const int b = blockIdx.x;
    const int i = b * SCAN_B + threadIdx.x;
    if (i >= NN) return;
    int rs = g_row_start[p * NN + i] + g_blksum[p * NBLK + b];
    g_row_start[p * NN + i] = rs;
    g_cursor   [p * NN + i] = rs;
}

// ---------------- 4. fill CSR (by dst) ----------------
__global__ void k_fill(const int* __restrict__ src, const int* __restrict__ dst) {
    int i = blockIdx.x * blockDim.x + threadIdx.x;
    if (i >= PP * EE) return;
    int p = i / EE;
    int d = dst[i];
    int pos = atomicAdd(&g_cursor[p * NN + d], 1);
    g_csr_src[(size_t)p * EE + pos] = src[i];
}

// ---------------- 5a. fp16 hi/lo split of h ---------------------------------
__global__ void k_split_h(const float* __restrict__ h) {
    size_t i = (size_t)blockIdx.x * blockDim.x + threadIdx.x;
    if (i >= (size_t)NN * CIN) return;
    float x = h[i];
    __half hi = __float2half_rn(x);
    __half lo = __float2half_rn(x - __half2float(hi));
    g_h_hi[i] = hi; g_h_lo[i] = lo;
}

// ---------------- 5b. fused weight prep -------------------------------------
__global__ void k_split_weights(const float* __restrict__ Wg,
                                const float* __restrict__ W1) {
    int i = blockIdx.x * blockDim.x + threadIdx.x;
    if (i < PP * CIN * DD) {
        int p = i / (CIN * DD);
        int r = i % (CIN * DD);
        int k = r / DD;
        int n = r % DD;
        g_wt[((size_t)p * DD + n) * CIN + k] = __float2half_rn(Wg[i]);
    }
    int j = i - PP * CIN * DD;
    if (j >= 0 && j < DD * SEMH) {
        int k = j / SEMH;
        int n = j % SEMH;
        float x = W1[j];
        __half hi = __float2half_rn(x);
        __half lo = __float2half_rn(x - __half2float(hi));
        size_t d = (size_t)n * DD + k;
        g_w1t_hi[d] = hi; g_w1t_lo[d] = lo;
    }
}

// ---------------- 6. tensor GEMM: x_p = fp16((h @ W_p) * rsqrt(deg_out)) ----
__global__ __launch_bounds__(256) void k_gemm_x(int p) {
    extern __shared__ __half smg[];
    const uint32_t sbase = smem_u32(smg);

    const int tid   = threadIdx.x;
    const int lane  = tid & 31;
    const int wid   = tid >> 5;
    const int wm    = wid & 3;
    const int wn    = wid >> 2;
    const int g     = lane >> 2;
    const int tig   = lane & 3;
    const int m0    = blockIdx.x * BM;
    const int n0    = blockIdx.y * BN;

    const __half* Wt = g_wt + (size_t)p * DD * CIN;

    float c[2][8][4];
#pragma unroll
    for (int mi = 0; mi < 2; mi++)
#pragma unroll
        for (int ni = 0; ni < 8; ni++)
#pragma unroll
            for (int j = 0; j < 4; j++) c[mi][ni][j] = 0.f;

    auto issue = [&](int kch, int buf) {
        const int k0 = kch * BK;
        const uint32_t b = sbase + (uint32_t)buf * 3u * TILE_BYTES;
#pragma unroll
        for (int it = 0; it < 2; it++) {
            int idx = tid + it * 256;
            int r  = idx >> 2;
            int cc = (idx & 3) * 8;
            uint32_t soff = (uint32_t)(r * SA + cc) * 2u;
            int sr = m0 + r;
            int ok = (sr < NN);
            size_t aoff = (size_t)(ok ? sr : 0) * CIN + k0 + cc;
            cp16(b + 0 * TILE_BYTES + soff, g_h_hi + aoff, ok ? 16 : 0);
            cp16(b + 1 * TILE_BYTES + soff, g_h_lo + aoff, ok ? 16 : 0);
            size_t boff = (size_t)(n0 + r) * CIN + k0 + cc;
            cp16(b + 2 * TILE_BYTES + soff, Wt + boff, 16);
        }
    };

    const int NK = CIN / BK;   // 8
    issue(0, 0);
    CP_COMMIT();
    for (int kc = 0; kc < NK; kc++) {
        const int buf = kc & 1;
        if (kc + 1 < NK) {
            issue(kc + 1, buf ^ 1);
            CP_COMMIT();
            CP_WAIT(1);
        } else {
            CP_WAIT(0);
        }
        __syncthreads();

        const __half* sAh = smg + (size_t)buf * 3 * TILE_ELEMS;
        const __half* sAl = sAh + TILE_ELEMS;
        const __half* sB  = sAl + TILE_ELEMS;

#pragma unroll
        for (int ks = 0; ks < BK; ks += 16) {
            const int c0 = ks + tig * 2;
            uint32_t ah[2][4], al[2][4];
#pragma unroll
            for (int mi = 0; mi < 2; mi++) {
                int r0 = wm * 32 + mi * 16 + g;
                ah[mi][0] = ld32(&sAh[r0 * SA + c0]);
                ah[mi][1] = ld32(&sAh[(r0 + 8) * SA + c0]);
                ah[mi][2] = ld32(&sAh[r0 * SA + c0 + 8]);
                ah[mi][3] = ld32(&sAh[(r0 + 8) * SA + c0 + 8]);
                al[mi][0] = ld32(&sAl[r0 * SA + c0]);
                al[mi][1] = ld32(&sAl[(r0 + 8) * SA + c0]);
                al[mi][2] = ld32(&sAl[r0 * SA + c0 + 8]);
                al[mi][3] = ld32(&sAl[(r0 + 8) * SA + c0 + 8]);
            }
#pragma unroll
            for (int ni = 0; ni < 8; ni++) {
                int nb = wn * 64 + ni * 8 + g;
                uint32_t b0 = ld32(&sB[nb * SA + c0]);
                uint32_t b1 = ld32(&sB[nb * SA + c0 + 8]);
#pragma unroll
                for (int mi = 0; mi < 2; mi++) {
                    mma_f16(c[mi][ni], ah[mi][0], ah[mi][1], ah[mi][2], ah[mi][3], b0, b1);
                    mma_f16(c[mi][ni], al[mi][0], al[mi][1], al[mi][2], al[mi][3], b0, b1);
                }
            }
        }
        __syncthreads();
    }

#pragma unroll
    for (int mi = 0; mi < 2; mi++) {
        int row0 = m0 + wm * 32 + mi * 16 + g;
        int row1 = row0 + 8;
        float rs0 = (row0 < NN) ? rsqrtf((float)max(g_deg_out[p * NN + row0], 1)) : 0.f;
        float rs1 = (row1 < NN) ? rsqrtf((float)max(g_deg_out[p * NN + row1], 1)) : 0.f;
#pragma unroll
        for (int ni = 0; ni < 8; ni++) {
            int col = n0 + wn * 64 + ni * 8 + tig * 2;
            if (row0 < NN) {
                __half2 v = __floats2half2_rn(c[mi][ni][0] * rs0, c[mi][ni][1] * rs0);
                *(__half2*)(g_x + ((size_t)p * NN + row0) * DD + col) = v;
            }
            if (row1 < NN) {
                __half2 v = __floats2half2_rn(c[mi][ni][2] * rs1, c[mi][ni][3] * rs1);
                *(__half2*)(g_x + ((size_t)p * NN + row1) * DD + col) = v;
            }
        }
    }
}

// ---------------- 7. aggregate: warp-per-node, lane = 8 dims (16B) ----------
__global__ __launch_bounds__(256) void k_agg(const float* __restrict__ b_gc, int p) {
    const int warp = threadIdx.x >> 5;
    const int lane = threadIdx.x & 31;
    const int n = blockIdx.x * 8 + warp;
    if (n >= NN) return;
    const int base  = p * NN + n;
    const int start = g_row_start[base];
    const int deg   = g_deg_in[base];
    const __half* X = g_x + (size_t)p * NN * DD;
    const int* cs   = g_csr_src + (size_t)p * EE + start;
    const int d0    = lane * 8;

    float acc[8] = {};
    int e = 0;
    for (; e + 4 <= deg; e += 4) {
        int s0 = cs[e], s1 = cs[e + 1], s2 = cs[e + 2], s3 = cs[e + 3];
        uint4 v0 = *(const uint4*)(X + (size_t)s0 * DD + d0);
        uint4 v1 = *(const uint4*)(X + (size_t)s1 * DD + d0);
        uint4 v2 = *(const uint4*)(X + (size_t)s2 * DD + d0);
        uint4 v3 = *(const uint4*)(X + (size_t)s3 * DD + d0);
#pragma unroll
        for (int q = 0; q < 4; q++) {
            float2 f0 = __half22float2(((__half2*)&v0)[q]);
            float2 f1 = __half22float2(((__half2*)&v1)[q]);
            float2 f2 = __half22float2(((__half2*)&v2)[q]);
            float2 f3 = __half22float2(((__half2*)&v3)[q]);
            acc[q * 2 + 0] += (f0.x + f1.x) + (f2.x + f3.x);
            acc[q * 2 + 1] += (f0.y + f1.y) + (f2.y + f3.y);
        }
    }
    for (; e < deg; e++) {
        uint4 v0 = *(const uint4*)(X + (size_t)cs[e] * DD + d0);
#pragma unroll
        for (int q = 0; q < 4; q++) {
            float2 f0 = __half22float2(((__half2*)&v0)[q]);
            acc[q * 2 + 0] += f0.x;
            acc[q * 2 + 1] += f0.y;
        }
    }

    float rs = rsqrtf((float)max(deg, 1));
    const float4 bA = *(const float4*)(b_gc + p * DD + d0);
    const float4 bB = *(const float4*)(b_gc + p * DD + d0 + 4);
    __half2 h0 = __floats2half2_rn(acc[0] * rs + bA.x, acc[1] * rs + bA.y);
    __half2 h1 = __floats2half2_rn(acc[2] * rs + bA.z, acc[3] * rs + bA.w);
    __half2 h2 = __floats2half2_rn(acc[4] * rs + bB.x, acc[5] * rs + bB.y);
    __half2 h3 = __floats2half2_rn(acc[6] * rs + bB.z, acc[7] * rs + bB.w);
    uint4 pk;
    pk.x = *(uint32_t*)&h0; pk.y = *(uint32_t*)&h1;
    pk.z = *(uint32_t*)&h2; pk.w = *(uint32_t*)&h3;
    *(uint4*)(g_z + ((size_t)p * NN + n) * DD + d0) = pk;
}

// ---------------- 8. semantic attention via fp16 mma (per-p, pipelined) -----
__global__ __launch_bounds__(256) void k_sem_tc(int p,
                                               const float* __restrict__ b1,
                                               const float* __restrict__ w2) {
    extern __shared__ __half sms[];
    const uint32_t sbase = smem_u32(sms);
    __shared__ float sred[128][9];
    __shared__ float sblk[128];

    const int tid  = threadIdx.x;
    const int lane = tid & 31;
    const int wid  = tid >> 5;
    const int wm   = wid & 3;
    const int wn   = wid >> 2;
    const int g    = lane >> 2;
    const int tig  = lane & 3;
    const int m0   = blockIdx.x * BM;

    const __half* Z = g_z + (size_t)p * NN * DD;

    float c[2][8][4];
#pragma unroll
    for (int mi = 0; mi < 2; mi++)
#pragma unroll
        for (int ni = 0; ni < 8; ni++)
#pragma unroll
            for (int j = 0; j < 4; j++) c[mi][ni][j] = 0.f;

    auto issue = [&](int kch, int buf) {
        const int k0 = kch * BK;
        const uint32_t b = sbase + (uint32_t)buf * 3u * TILE_BYTES;
#pragma unroll
        for (int it = 0; it < 2; it++) {
            int idx = tid + it * 256;
            int r  = idx >> 2;
            int cc = (idx & 3) * 8;
            uint32_t soff = (uint32_t)(r * SA + cc) * 2u;
            int sr = m0 + r;
            int ok = (sr < NN);
            size_t aoff = (size_t)(ok ? sr : 0) * DD + k0 + cc;
            cp16(b + 0 * TILE_BYTES + soff, Z + aoff, ok ? 16 : 0);
            size_t boff = (size_t)r * DD + k0 + cc;
            cp16(b + 1 * TILE_BYTES + soff, g_w1t_hi + boff, 16);
            cp16(b + 2 * TILE_BYTES + soff, g_w1t_lo + boff, 16);
        }
    };

    const int NK = DD / BK;   // 8
    issue(0, 0);
    CP_COMMIT();
    for (int kc = 0; kc < NK; kc++) {
        const int buf = kc & 1;
        if (kc + 1 < NK) {
            issue(kc + 1, buf ^ 1);
            CP_COMMIT();
            CP_WAIT(1);
        } else {
            CP_WAIT(0);
        }
        __syncthreads();

        const __half* sA  = sms + (size_t)buf * 3 * TILE_ELEMS;
        const __half* sBh = sA + TILE_ELEMS;
        const __half* sBl = sBh + TILE_ELEMS;

#pragma unroll
        for (int ks = 0; ks < BK; ks += 16) {
            const int c0 = ks + tig * 2;
            uint32_t a[2][4];
#pragma unroll
            for (int mi = 0; mi < 2; mi++) {
                int r0 = wm * 32 + mi * 16 + g;
                a[mi][0] = ld32(&sA[r0 * SA + c0]);
                a[mi][1] = ld32(&sA[(r0 + 8) * SA + c0]);
                a[mi][2] = ld32(&sA[r0 * SA + c0 + 8]);
                a[mi][3] = ld32(&sA[(r0 + 8) * SA + c0 + 8]);
            }
#pragma unroll
            for (int ni = 0; ni < 8; ni++) {
                int nb = wn * 64 + ni * 8 + g;
                uint32_t bh0 = ld32(&sBh[nb * SA + c0]);
                uint32_t bh1 = ld32(&sBh[nb * SA + c0 + 8]);
                uint32_t bl0 = ld32(&sBl[nb * SA + c0]);
                uint32_t bl1 = ld32(&sBl[nb * SA + c0 + 8]);
#pragma unroll
                for (int mi = 0; mi < 2; mi++) {
                    mma_f16(c[mi][ni], a[mi][0], a[mi][1], a[mi][2], a[mi][3], bh0, bh1);
                    mma_f16(c[mi][ni], a[mi][0], a[mi][1], a[mi][2], a[mi][3], bl0, bl1);
                }
            }
        }
        __syncthreads();
    }

    float vrow[2][2] = {{0.f, 0.f}, {0.f, 0.f}};
#pragma unroll
    for (int ni = 0; ni < 8; ni++) {
        int col = wn * 64 + ni * 8 + tig * 2;
        float b1a = b1[col], b1b = b1[col + 1];
        float w2a = w2[col], w2b = w2[col + 1];
#pragma unroll
        for (int mi = 0; mi < 2; mi++) {
            vrow[mi][0] += tanhf(c[mi][ni][0] + b1a) * w2a + tanhf(c[mi][ni][1] + b1b) * w2b;
            vrow[mi][1] += tanhf(c[mi][ni][2] + b1a) * w2a + tanhf(c[mi][ni][3] + b1b) * w2b;
        }
    }
#pragma unroll
    for (int mi = 0; mi < 2; mi++) {
        int r0 = wm * 32 + mi * 16 + g;
        sred[r0][wn * 4 + tig]     = vrow[mi][0];
        sred[r0 + 8][wn * 4 + tig] = vrow[mi][1];
    }
    __syncthreads();
    if (tid < 128) {
        float sv = 0.f;
        if (m0 + tid < NN) {
#pragma unroll
            for (int t = 0; t < 8; t++) sv += sred[tid][t];
        }
        sblk[tid] = sv;
    }
    __syncthreads();
    for (int off = 64; off > 0; off >>= 1) {
        if (tid < off) sblk[tid] += sblk[tid + off];
        __syncthreads();
    }
    if (tid == 0) atomicAdd(&g_s_sum[p], sblk[0]);
}

// ---------------- 9. beta = softmax(mean over nodes) ------------------------
__global__ void k_beta() {
    if (threadIdx.x == 0 && blockIdx.x == 0) {
        float m[PP]; float mx = -1e30f;
        for (int p = 0; p < PP; p++) { m[p] = g_s_sum[p] / (float)NN; mx = fmaxf(mx, m[p]); }
        float se = 0.f;
        for (int p = 0; p < PP; p++) { m[p] = expf(m[p] - mx); se += m[p]; }
        for (int p = 0; p < PP; p++) g_beta[p] = m[p] / se;
    }
}

// ---------------- 10. combine: out = sum_p beta[p] * z_p (fp16 -> fp32) -----
__global__ void k_comb(float* __restrict__ out) {
    const size_t q = (size_t)NN * DD / 4;
    size_t i = (size_t)blockIdx.x * blockDim.x + threadIdx.x;
    if (i >= q) return;
    float b0 = g_beta[0], b1 = g_beta[1], b2 = g_beta[2], b3 = g_beta[3];
    const uint2* z = (const uint2*)g_z;
    uint2 u0 = z[i], u1 = z[q + i], u2 = z[2 * q + i], u3 = z[3 * q + i];
    float2 p0a = __half22float2(*(__half2*)&u0.x), p0b = __half22float2(*(__half2*)&u0.y);
    float2 p1a = __half22float2(*(__half2*)&u1.x), p1b = __half22float2(*(__half2*)&u1.y);
    float2 p2a = __half22float2(*(__half2*)&u2.x), p2b = __half22float2(*(__half2*)&u2.y);
    float2 p3a = __half22float2(*(__half2*)&u3.x), p3b = __half22float2(*(__half2*)&u3.y);
    float4 o;
    o.x = b0 * p0a.x + b1 * p1a.x + b2 * p2a.x + b3 * p3a.x;
    o.y = b0 * p0a.y + b1 * p1a.y + b2 * p2a.y + b3 * p3a.y;
    o.z = b0 * p0b.x + b1 * p1b.x + b2 * p2b.x + b3 * p3b.x;
    o.w = b0 * p0b.y + b1 * p1b.y + b2 * p2b.y + b3 * p3b.y;
    ((float4*)out)[i] = o;
}

// ---------------- launch ----------------------------------------------------
extern "C" void kernel_launch(void* const* d_in, const int* in_sizes, int n_in,
                              void* d_out, int out_size) {
    const float* h    = (const float*)d_in[0];
    const int*   src  = (const int*)  d_in[1];
    const int*   dst  = (const int*)  d_in[2];
    const float* W_gc = (const float*)d_in[3];
    const float* b_gc = (const float*)d_in[4];
    const float* W1   = (const float*)d_in[5];
    const float* b1   = (const float*)d_in[6];
    const float* w2   = (const float*)d_in[7];
    float* out = (float*)d_out;

    static cudaStream_t s1 = nullptr, s2 = nullptr, s3 = nullptr;
    static cudaEvent_t ev0, evDeg, evCsr, evG[PP], evA[PP], evSemDone;
    if (!s1) {
        cudaStreamCreateWithFlags(&s1, cudaStreamNonBlocking);
        cudaStreamCreateWithFlags(&s2, cudaStreamNonBlocking);
        cudaStreamCreateWithFlags(&s3, cudaStreamNonBlocking);
        cudaEventCreateWithFlags(&ev0,   cudaEventDisableTiming);
        cudaEventCreateWithFlags(&evDeg, cudaEventDisableTiming);
        cudaEventCreateWithFlags(&evCsr, cudaEventDisableTiming);
        for (int p = 0; p < PP; p++) {
            cudaEventCreateWithFlags(&evG[p], cudaEventDisableTiming);
            cudaEventCreateWithFlags(&evA[p], cudaEventDisableTiming);
        }
        cudaEventCreateWithFlags(&evSemDone, cudaEventDisableTiming);
        cudaFuncSetAttribute(k_gemm_x, cudaFuncAttributeMaxDynamicSharedMemorySize,
                             GEMM_SMEM);
        cudaFuncSetAttribute(k_sem_tc, cudaFuncAttributeMaxDynamicSharedMemorySize,
                             GEMM_SMEM);
    }

    // stream 0: zero counters, fork
    k_zero<<<(PP * NN + 255) / 256, 256>>>();
    cudaEventRecord(ev0, 0);
    cudaStreamWaitEvent(s1, ev0, 0);

    // s1: CSR chain (deg -> scan -> fill)
    k_deg<<<(PP * EE + 255) / 256, 256, 0, s1>>>(src, dst);
    cudaEventRecord(evDeg, s1);
    k_scan1<<<dim3(NBLK, PP), SCAN_B, 0, s1>>>();
    k_scan2<<<1, PP * 32, 0, s1>>>();
    k_scan3<<<dim3(NBLK, PP), SCAN_B, 0, s1>>>();
    k_fill<<<(PP * EE + 255) / 256, 256, 0, s1>>>(src, dst);
    cudaEventRecord(evCsr, s1);

    // s2: prep (independent of zero) then all 4 GEMMs (need deg_out)
    k_split_h<<<(int)(((size_t)NN * CIN + 255) / 256), 256, 0, s2>>>(h);
    k_split_weights<<<(PP * CIN * DD + DD * SEMH + 255) / 256, 256, 0, s2>>>(W_gc, W1);
    cudaStreamWaitEvent(s2, evDeg, 0);
    for (int p = 0; p < PP; p++) {
        k_gemm_x<<<dim3(MTILES, DD / BN), 256, GEMM_SMEM, s2>>>(p);
        cudaEventRecord(evG[p], s2);
    }

    // stream 0: agg pipeline (needs CSR + gemm(p))
    cudaStreamWaitEvent(0, evCsr, 0);
    for (int p = 0; p < PP; p++) {
        cudaStreamWaitEvent(0, evG[p], 0);
        k_agg<<<(NN + 7) / 8, 256>>>(b_gc, p);
        cudaEventRecord(evA[p], 0);
        // s3: sem(p) as soon as agg(p) done
        cudaStreamWaitEvent(s3, evA[p], 0);
        k_sem_tc<<<MTILES, 256, GEMM_SMEM, s3>>>(p, b1, w2);
    }
    cudaEventRecord(evSemDone, s3);

    // stream 0: join everything, then beta + combine
    cudaStreamWaitEvent(0, evSemDone, 0);
    k_beta<<<1, 32>>>();
    k_comb<<<(int)(((size_t)NN * DD / 4 + 255) / 256), 256>>>(out);
}